// round 10
// baseline (speedup 1.0000x reference)
#include <cuda_runtime.h>
#include <cuda_bf16.h>
#include <cuda_fp8.h>
#include <cstdint>
#include <math.h>

#define BATCH 32768
#define D_IN  1024
#define D_H   1024
#define D_L   128

// ---------------- scratch (__device__ globals; alloc-free rule) -------------
__device__ __align__(16) uint8_t       g_xb8 [BATCH * D_IN];     // x in e4m3 (exact 0/1)
__device__ __align__(16) __nv_bfloat16 g_hb  [BATCH * D_H];
__device__ __align__(16) uint8_t       g_hdb8[BATCH * D_H];      // hd in e4m3, x16
__device__ __align__(16) float         g_kl  [BATCH];
__device__ __align__(16) float         g_lp  [BATCH * 16];
__device__ __align__(16) uint8_t       g_We1t8[D_H * D_IN];      // [N][K] K-major e4m3 x64
__device__ __align__(16) __nv_bfloat16 g_Wmlt[256 * D_H];        // bf16
__device__ __align__(16) __nv_bfloat16 g_Wd1t[D_H * D_L];        // bf16
__device__ __align__(16) uint8_t       g_Wd2t8[D_IN * D_H];      // e4m3 x64
__device__ __align__(16) float         g_bml [256];

static constexpr float W_SCALE  = 64.f;
static constexpr float HD_SCALE = 16.f;

// ---------------- helpers ----------------------------------------------------
__device__ __forceinline__ uint32_t smem_u32(const void* p) {
    uint32_t a;
    asm("{ .reg .u64 t; cvta.to.shared.u64 t, %1; cvt.u32.u64 %0, t; }" : "=r"(a) : "l"(p));
    return a;
}

#define CP_ASYNC16(dst, src) \
    asm volatile("cp.async.cg.shared.global [%0], [%1], 16;" :: "r"(dst), "l"(src))
#define CP_COMMIT() asm volatile("cp.async.commit_group;" ::: "memory")
#define CP_WAIT0()  asm volatile("cp.async.wait_group 0;" ::: "memory")
#define CP_WAIT1()  asm volatile("cp.async.wait_group 1;" ::: "memory")

__device__ __forceinline__ void ldsm4(uint32_t& r0, uint32_t& r1, uint32_t& r2, uint32_t& r3,
                                      uint32_t addr) {
    asm volatile("ldmatrix.sync.aligned.m8n8.x4.shared.b16 {%0,%1,%2,%3}, [%4];"
                 : "=r"(r0), "=r"(r1), "=r"(r2), "=r"(r3) : "r"(addr));
}

template<bool FP8>
__device__ __forceinline__ void mma_step(float* c, const uint32_t* a, const uint32_t* b) {
    if constexpr (FP8) {
        asm volatile("mma.sync.aligned.m16n8k32.row.col.f32.e4m3.e4m3.f32 "
                     "{%0,%1,%2,%3}, {%4,%5,%6,%7}, {%8,%9}, {%0,%1,%2,%3};"
                     : "+f"(c[0]), "+f"(c[1]), "+f"(c[2]), "+f"(c[3])
                     : "r"(a[0]), "r"(a[1]), "r"(a[2]), "r"(a[3]), "r"(b[0]), "r"(b[1]));
    } else {
        asm volatile("mma.sync.aligned.m16n8k16.row.col.f32.bf16.bf16.f32 "
                     "{%0,%1,%2,%3}, {%4,%5,%6,%7}, {%8,%9}, {%0,%1,%2,%3};"
                     : "+f"(c[0]), "+f"(c[1]), "+f"(c[2]), "+f"(c[3])
                     : "r"(a[0]), "r"(a[1]), "r"(a[2]), "r"(a[3]), "r"(b[0]), "r"(b[1]));
    }
}

// ---------------- HMMA GEMM: C[M,N] = A[M,K] @ Bt[N,K]^T (+epilogue) ---------
// K-chunk = 128 BYTES per row (64 bf16 or 128 e4m3): identical smem layout,
// swizzle, ldsm addressing for both dtypes (k32-fp8 frag == k16-bf16 frag).
// Warp tile 64x64. EPI 0/2: BM=BN=128, 128 thr, 2 CTA/SM. EPI 3: 128x256, 256 thr.
// EPI 0: bf16 relu(acc*scale+bias)
// EPI 2: Bernoulli partial (x from e4m3 bytes) -> LP[row*16 + bn*2 + wn]
// EPI 3: fused reparam + KL + hd = relu(z @ W2^T + B2)*16 -> C2 (e4m3)
static constexpr int NSTAGE = 3;

template<int BM, int BN> struct GemmCfg {
    static constexpr int STAGE = (BM + BN) * 128;   // 128 bytes per row per tile
    static constexpr int SMEM  = NSTAGE * STAGE + 128;
};

template<int EPI, bool FP8, int BM, int BN, int NTHR, int MINB>
__global__ __launch_bounds__(NTHR, MINB)
void mma_gemm(const void* __restrict__ A, int lda,
              const void* __restrict__ Bt,
              const float* __restrict__ bias, float scale,
              void* __restrict__ Cv, int ldc,
              const uint8_t* __restrict__ XB,
              float* __restrict__ LP,
              const float* __restrict__ EPS,
              const __nv_bfloat16* __restrict__ W2,
              const float* __restrict__ B2,
              uint8_t* __restrict__ C2, int K)
{
    extern __shared__ char smraw[];
    uint32_t raw = smem_u32(smraw);
    uint32_t sbase = (raw + 127u) & ~127u;
    char* sm = smraw + (sbase - raw);

    constexpr int ESZ = FP8 ? 1 : 2;
    constexpr int NWARP = NTHR / 32;
    constexpr int WM  = 2;
    constexpr int WNG = NWARP / WM;
    constexpr int WTN = BN / WNG;              // 64
    constexpr int NT  = WTN / 8;               // 8
    constexpr int BLD = WTN / 16;              // 4
    constexpr int A_BYTES = BM * 128;
    constexpr int STAGE_BYTES = GemmCfg<BM, BN>::STAGE;
    constexpr int AI = BM * 8 / NTHR, BI = BN * 8 / NTHR;

    const int tid  = threadIdx.x, lane = tid & 31, wid = tid >> 5;
    const int wm   = wid % WM, wn = wid / WM;
    const int bn   = blockIdx.x;
    const int m0   = blockIdx.y * BM, col0 = bn * BN;

    const size_t ldaB = (size_t)lda * ESZ, ldbB = (size_t)K * ESZ;
    const char* Ab = (const char*)A  + (size_t)m0   * ldaB;
    const char* Bb = (const char*)Bt + (size_t)col0 * ldbB;

    const int T = (int)(((size_t)K * ESZ) >> 7);   // 128-byte K chunks
    const int P = (T < NSTAGE - 1) ? T : (NSTAGE - 1);

    float acc[4][NT][4];
#pragma unroll
    for (int mt = 0; mt < 4; ++mt)
#pragma unroll
        for (int nt = 0; nt < NT; ++nt)
#pragma unroll
            for (int q = 0; q < 4; ++q) acc[mt][nt][q] = 0.f;

    auto issue_stage = [&](int kt) {
        uint32_t sA = sbase + (uint32_t)(kt % NSTAGE) * STAGE_BYTES;
        uint32_t sB = sA + A_BYTES;
        const char* Ak = Ab + (size_t)kt * 128;
        const char* Bk = Bb + (size_t)kt * 128;
#pragma unroll
        for (int i = 0; i < AI; ++i) {
            int idx = tid + i * NTHR;
            int rr = idx >> 3, cc = idx & 7;
            uint32_t sw = (uint32_t)(rr * 128 + ((cc ^ (rr & 7)) << 4));
            CP_ASYNC16(sA + sw, Ak + (size_t)rr * ldaB + cc * 16);
        }
#pragma unroll
        for (int i = 0; i < BI; ++i) {
            int idx = tid + i * NTHR;
            int rr = idx >> 3, cc = idx & 7;
            uint32_t sw = (uint32_t)(rr * 128 + ((cc ^ (rr & 7)) << 4));
            CP_ASYNC16(sB + sw, Bk + (size_t)rr * ldbB + cc * 16);
        }
        CP_COMMIT();
    };

    for (int kt = 0; kt < P; ++kt) issue_stage(kt);
    int committed = P;

    const int g = lane >> 3, lq = lane & 7;

    for (int t = 0; t < T; ++t) {
        int allow = committed - t - 1;
        if (allow >= 1) { CP_WAIT1(); } else { CP_WAIT0(); }
        __syncthreads();

        if (t + NSTAGE - 1 < T) { issue_stage(t + NSTAGE - 1); committed++; }

        uint32_t sA = sbase + (uint32_t)(t % NSTAGE) * STAGE_BYTES;
        uint32_t sB = sA + A_BYTES;

#pragma unroll
        for (int kk = 0; kk < 4; ++kk) {
            uint32_t a[4][4];
#pragma unroll
            for (int mt = 0; mt < 4; ++mt) {
                int row = wm * 64 + mt * 16 + (g & 1) * 8 + lq;
                int kc  = kk * 2 + (g >> 1);
                uint32_t ad = sA + (uint32_t)(row * 128 + ((kc ^ (row & 7)) << 4));
                ldsm4(a[mt][0], a[mt][1], a[mt][2], a[mt][3], ad);
            }
            uint32_t b[NT][2];
#pragma unroll
            for (int p = 0; p < BLD; ++p) {
                int row = wn * WTN + (p * 2 + (g >> 1)) * 8 + lq;
                int kc  = kk * 2 + (g & 1);
                uint32_t ad = sB + (uint32_t)(row * 128 + ((kc ^ (row & 7)) << 4));
                uint32_t r0, r1, r2, r3;
                ldsm4(r0, r1, r2, r3, ad);
                b[p * 2][0] = r0; b[p * 2][1] = r1;
                b[p * 2 + 1][0] = r2; b[p * 2 + 1][1] = r3;
            }
#pragma unroll
            for (int mt = 0; mt < 4; ++mt)
#pragma unroll
                for (int nt = 0; nt < NT; ++nt)
                    mma_step<FP8>(acc[mt][nt], a[mt], b[nt]);
        }
    }

    // ---------------- epilogue ----------------
    const int rbase = m0 + wm * 64 + (lane >> 2);
    const int cq    = (lane & 3) * 2;

    if (EPI == 0) {
        __nv_bfloat16* C = (__nv_bfloat16*)Cv;
#pragma unroll
        for (int mt = 0; mt < 4; ++mt) {
            int r0 = rbase + mt * 16;
#pragma unroll
            for (int nt = 0; nt < NT; ++nt) {
                int col = col0 + wn * WTN + nt * 8 + cq;
                float b0 = __ldg(bias + col), b1 = __ldg(bias + col + 1);
                float v0 = fmaxf(fmaf(acc[mt][nt][0], scale, b0), 0.f);
                float v1 = fmaxf(fmaf(acc[mt][nt][1], scale, b1), 0.f);
                float v2 = fmaxf(fmaf(acc[mt][nt][2], scale, b0), 0.f);
                float v3 = fmaxf(fmaf(acc[mt][nt][3], scale, b1), 0.f);
                __nv_bfloat162 p0 = __float22bfloat162_rn(make_float2(v0, v1));
                __nv_bfloat162 p1 = __float22bfloat162_rn(make_float2(v2, v3));
                *(uint32_t*)(C + (size_t)r0 * ldc + col)       = *(uint32_t*)&p0;
                *(uint32_t*)(C + (size_t)(r0 + 8) * ldc + col) = *(uint32_t*)&p1;
            }
        }
    } else if (EPI == 2) {
#pragma unroll
        for (int mt = 0; mt < 4; ++mt) {
            int r0 = rbase + mt * 16;
            float s0 = 0.f, s1 = 0.f;
#pragma unroll
            for (int nt = 0; nt < NT; ++nt) {
                int col = col0 + wn * WTN + nt * 8 + cq;
                float b0 = __ldg(bias + col), b1 = __ldg(bias + col + 1);
                uint16_t xw0 = *(const uint16_t*)(XB + (size_t)r0 * D_IN + col);
                uint16_t xw1 = *(const uint16_t*)(XB + (size_t)(r0 + 8) * D_IN + col);
                float a0 = fmaf(acc[mt][nt][0], scale, b0);
                float a1 = fmaf(acc[mt][nt][1], scale, b1);
                float a2 = fmaf(acc[mt][nt][2], scale, b0);
                float a3 = fmaf(acc[mt][nt][3], scale, b1);
                float t0 = (xw0 & 0x00ffu) ? -a0 : a0;
                float t1 = (xw0 & 0xff00u) ? -a1 : a1;
                float t2 = (xw1 & 0x00ffu) ? -a2 : a2;
                float t3 = (xw1 & 0xff00u) ? -a3 : a3;
                s0 += fmaxf(t0, 0.f) + log1pf(__expf(-fabsf(t0)));
                s0 += fmaxf(t1, 0.f) + log1pf(__expf(-fabsf(t1)));
                s1 += fmaxf(t2, 0.f) + log1pf(__expf(-fabsf(t2)));
                s1 += fmaxf(t3, 0.f) + log1pf(__expf(-fabsf(t3)));
            }
            s0 += __shfl_xor_sync(0xffffffffu, s0, 1);
            s0 += __shfl_xor_sync(0xffffffffu, s0, 2);
            s1 += __shfl_xor_sync(0xffffffffu, s1, 1);
            s1 += __shfl_xor_sync(0xffffffffu, s1, 2);
            if ((lane & 3) == 0) {
                LP[(size_t)r0 * 16 + bn * 2 + wn]       = -s0;
                LP[(size_t)(r0 + 8) * 16 + bn * 2 + wn] = -s1;
            }
        }
    } else {
        // EPI 3: fused reparam + KL + hd GEMM (all bf16). BM=128, BN=256, NTHR=256.
        constexpr int SPAD = 258;
        float* S = (float*)sm;
        __syncthreads();
        const int rl = wm * 64 + (lane >> 2);
#pragma unroll
        for (int mt = 0; mt < 4; ++mt) {
            int r0 = rl + mt * 16;
#pragma unroll
            for (int nt = 0; nt < NT; ++nt) {
                int col = wn * WTN + nt * 8 + cq;
                float b0 = __ldg(bias + col), b1 = __ldg(bias + col + 1);
                *(float2*)&S[(size_t)r0 * SPAD + col] =
                    make_float2(acc[mt][nt][0] + b0, acc[mt][nt][1] + b1);
                *(float2*)&S[(size_t)(r0 + 8) * SPAD + col] =
                    make_float2(acc[mt][nt][2] + b0, acc[mt][nt][3] + b1);
            }
        }
        __syncthreads();

        const int r = tid >> 1, h = tid & 1;
        const size_t grow = (size_t)m0 + r;
        const float* erow = EPS + grow * 128 + h * 64;
        float kla = 0.f;
        uint32_t zbuf[32];
#pragma unroll
        for (int j = 0; j < 32; ++j) {
            int c = h * 64 + 2 * j;
            float mu0 = S[(size_t)r * SPAD + c];
            float mu1 = S[(size_t)r * SPAD + c + 1];
            float l0  = S[(size_t)r * SPAD + c + 128];
            float l1  = S[(size_t)r * SPAD + c + 129];
            float2 ep = *(const float2*)&erow[2 * j];
            float s0 = expf(l0), s1 = expf(l1);
            float z0 = fmaf(s0, ep.x, mu0), z1 = fmaf(s1, ep.y, mu1);
            __nv_bfloat162 p = __float22bfloat162_rn(make_float2(z0, z1));
            zbuf[j] = *(uint32_t*)&p;
            kla += s0 * s0 + mu0 * mu0 - 2.f * l0 - 1.f;
            kla += s1 * s1 + mu1 * mu1 - 2.f * l1 - 1.f;
        }
        kla += __shfl_xor_sync(0xffffffffu, kla, 1);
        if (h == 0) LP[grow] = 0.5f * kla;
        __syncthreads();

        // stage z (bf16) into smem as two swizzled A-chunks (16KB each)
#pragma unroll
        for (int cc = 0; cc < 8; ++cc) {
            uint32_t off = (uint32_t)h * 16384u +
                           (uint32_t)(r * 128 + ((cc ^ (r & 7)) << 4));
            *(int4*)(sm + off) = ((int4*)zbuf)[cc];
        }

        auto issue_b = [&](int nb) {
            uint32_t sB = sbase + 32768u + (uint32_t)(nb % 3) * 32768u;
            const __nv_bfloat16* Bk = W2 + (size_t)(nb * 128) * 128;
#pragma unroll
            for (int i = 0; i < 2048 / NTHR; ++i) {
                int idx = tid + i * NTHR;
                int tt = idx >> 10;
                int rr = (idx >> 3) & 127;
                int cc = idx & 7;
                uint32_t sw = (uint32_t)(rr * 128 + ((cc ^ (rr & 7)) << 4));
                CP_ASYNC16(sB + (uint32_t)tt * 16384u + sw,
                           Bk + (size_t)rr * 128 + tt * 64 + cc * 8);
            }
            CP_COMMIT();
        };
        issue_b(0); issue_b(1);

        for (int nb = 0; nb < 8; ++nb) {
            if (nb < 7) { CP_WAIT1(); } else { CP_WAIT0(); }
            __syncthreads();
            if (nb + 2 < 8) issue_b(nb + 2);

            uint32_t sB = sbase + 32768u + (uint32_t)(nb % 3) * 32768u;
            float acc2[4][4][4];
#pragma unroll
            for (int mt = 0; mt < 4; ++mt)
#pragma unroll
                for (int nt = 0; nt < 4; ++nt)
#pragma unroll
                    for (int q = 0; q < 4; ++q) acc2[mt][nt][q] = 0.f;

#pragma unroll
            for (int t = 0; t < 2; ++t) {
#pragma unroll
                for (int kk = 0; kk < 4; ++kk) {
                    uint32_t a[4][4];
#pragma unroll
                    for (int mt = 0; mt < 4; ++mt) {
                        int row = wm * 64 + mt * 16 + (g & 1) * 8 + lq;
                        int kc  = kk * 2 + (g >> 1);
                        uint32_t ad = sbase + (uint32_t)t * 16384u +
                                      (uint32_t)(row * 128 + ((kc ^ (row & 7)) << 4));
                        ldsm4(a[mt][0], a[mt][1], a[mt][2], a[mt][3], ad);
                    }
                    uint32_t b[4][2];
#pragma unroll
                    for (int p = 0; p < 2; ++p) {
                        int row = wn * 32 + (p * 2 + (g >> 1)) * 8 + lq;
                        int kc  = kk * 2 + (g & 1);
                        uint32_t ad = sB + (uint32_t)t * 16384u +
                                      (uint32_t)(row * 128 + ((kc ^ (row & 7)) << 4));
                        uint32_t r0, r1, r2, r3;
                        ldsm4(r0, r1, r2, r3, ad);
                        b[p * 2][0] = r0; b[p * 2][1] = r1;
                        b[p * 2 + 1][0] = r2; b[p * 2 + 1][1] = r3;
                    }
#pragma unroll
                    for (int mt = 0; mt < 4; ++mt)
#pragma unroll
                        for (int nt = 0; nt < 4; ++nt)
                            mma_step<false>(acc2[mt][nt], a[mt], b[nt]);
                }
            }
            // store hd as e4m3 x16
#pragma unroll
            for (int mt = 0; mt < 4; ++mt) {
                int r0 = rbase + mt * 16;
#pragma unroll
                for (int nt = 0; nt < 4; ++nt) {
                    int col = nb * 128 + wn * 32 + nt * 8 + cq;
                    float b0 = __ldg(B2 + col), b1 = __ldg(B2 + col + 1);
                    float v0 = fmaxf(acc2[mt][nt][0] + b0, 0.f) * HD_SCALE;
                    float v1 = fmaxf(acc2[mt][nt][1] + b1, 0.f) * HD_SCALE;
                    float v2 = fmaxf(acc2[mt][nt][2] + b0, 0.f) * HD_SCALE;
                    float v3 = fmaxf(acc2[mt][nt][3] + b1, 0.f) * HD_SCALE;
                    __nv_fp8x2_storage_t q0 =
                        __nv_cvt_float2_to_fp8x2(make_float2(v0, v1), __NV_SATFINITE, __NV_E4M3);
                    __nv_fp8x2_storage_t q1 =
                        __nv_cvt_float2_to_fp8x2(make_float2(v2, v3), __NV_SATFINITE, __NV_E4M3);
                    *(uint16_t*)(C2 + (size_t)r0 * D_H + col)       = q0;
                    *(uint16_t*)(C2 + (size_t)(r0 + 8) * D_H + col) = q1;
                }
            }
        }
    }
}

// ---------------- fused prep kernel ------------------------------------------
__device__ __forceinline__ void do_transpose_bf16(float (*ts)[33],
        const float* __restrict__ in, __nv_bfloat16* __restrict__ out,
        int K, int N, int rowOff, int bx, int by, int tid) {
    int tx = tid & 31, ty = tid >> 5;
    int k0 = by * 32, n0 = bx * 32;
    for (int j = ty; j < 32; j += 8)
        ts[j][tx] = in[(size_t)(k0 + j) * N + n0 + tx];
    __syncthreads();
    for (int j = ty; j < 32; j += 8)
        out[(size_t)(rowOff + n0 + j) * K + k0 + tx] = __float2bfloat16(ts[tx][j]);
}

__device__ __forceinline__ void do_transpose_fp8(float (*ts)[33],
        const float* __restrict__ in, uint8_t* __restrict__ out,
        int K, int N, int bx, int by, int tid) {
    int tx = tid & 31, ty = tid >> 5;
    int k0 = by * 32, n0 = bx * 32;
    for (int j = ty; j < 32; j += 8)
        ts[j][tx] = in[(size_t)(k0 + j) * N + n0 + tx];
    __syncthreads();
    for (int j = ty; j < 32; j += 8)
        out[(size_t)(n0 + j) * K + k0 + tx] =
            __nv_cvt_float_to_fp8(ts[tx][j] * W_SCALE, __NV_SATFINITE, __NV_E4M3);
}

__global__ __launch_bounds__(256)
void prep_kernel(const float* __restrict__ x,
                 const float* __restrict__ We1, const float* __restrict__ Wmu,
                 const float* __restrict__ Wls, const float* __restrict__ Wd1,
                 const float* __restrict__ Wd2, const float* __restrict__ bmu,
                 const float* __restrict__ bls,
                 uint8_t* __restrict__ xb8, uint8_t* __restrict__ We1t8,
                 __nv_bfloat16* __restrict__ Wmlt, __nv_bfloat16* __restrict__ Wd1t,
                 uint8_t* __restrict__ Wd2t8, float* __restrict__ bml)
{
    __shared__ float ts[32][33];
    const int b = blockIdx.x, tid = threadIdx.x;
    if (b < 16384) {
        size_t i = ((size_t)b * 256 + tid) * 8;
        float4 a = *(const float4*)(x + i);
        float4 c = *(const float4*)(x + i + 4);
        // binary x: e4m3 1.0 = 0x38, 0.0 = 0x00 (exact)
        uint32_t lo = (a.x > 0.5f ? 0x38u : 0u)        | (a.y > 0.5f ? 0x3800u : 0u)
                    | (a.z > 0.5f ? 0x380000u : 0u)    | (a.w > 0.5f ? 0x38000000u : 0u);
        uint32_t hi = (c.x > 0.5f ? 0x38u : 0u)        | (c.y > 0.5f ? 0x3800u : 0u)
                    | (c.z > 0.5f ? 0x380000u : 0u)    | (c.w > 0.5f ? 0x38000000u : 0u);
        uint2 w = make_uint2(lo, hi);
        *(uint2*)(xb8 + i) = w;
    } else if (b < 17408) {
        int r = b - 16384;  do_transpose_fp8(ts, We1, We1t8, 1024, 1024, r % 32, r / 32, tid);
    } else if (b < 17536) {
        int r = b - 17408;  do_transpose_bf16(ts, Wmu, Wmlt, 1024, 128,  0,   r % 4,  r / 4,  tid);
    } else if (b < 17664) {
        int r = b - 17536;  do_transpose_bf16(ts, Wls, Wmlt, 1024, 128,  128, r % 4,  r / 4,  tid);
    } else if (b < 17792) {
        int r = b - 17664;  do_transpose_bf16(ts, Wd1, Wd1t, 128,  1024, 0,   r % 32, r / 32, tid);
    } else if (b < 18816) {
        int r = b - 17792;  do_transpose_fp8(ts, Wd2, Wd2t8, 1024, 1024, r % 32, r / 32, tid);
    } else {
        bml[tid] = (tid < 128) ? bmu[tid] : bls[tid - 128];
    }
}

__global__ void finalize_kernel(const float* __restrict__ kl_, const float* __restrict__ lp_,
                                float* __restrict__ out) {
    int r = blockIdx.x * blockDim.x + threadIdx.x;
    float s = 0.f;
#pragma unroll
    for (int j = 0; j < 16; j++) s += lp_[(size_t)r * 16 + j];
    out[r] = s - kl_[r];
}

// ---------------- launch ------------------------------------------------------
extern "C" void kernel_launch(void* const* d_in, const int* in_sizes, int n_in,
                              void* d_out, int out_size)
{
    const float* x   = (const float*)d_in[0];
    const float* eps = (const float*)d_in[1];
    const float* We1 = (const float*)d_in[2];
    const float* be1 = (const float*)d_in[3];
    const float* Wmu = (const float*)d_in[4];
    const float* bmu = (const float*)d_in[5];
    const float* Wls = (const float*)d_in[6];
    const float* bls = (const float*)d_in[7];
    const float* Wd1 = (const float*)d_in[8];
    const float* bd1 = (const float*)d_in[9];
    const float* Wd2 = (const float*)d_in[10];
    const float* bd2 = (const float*)d_in[11];
    float* out = (float*)d_out;

    uint8_t *xb8, *hdb8, *We1t8, *Wd2t8;
    __nv_bfloat16 *hb, *Wmlt, *Wd1t;
    float *kl, *lp, *bml;
    cudaGetSymbolAddress((void**)&xb8,   g_xb8);
    cudaGetSymbolAddress((void**)&hb,    g_hb);
    cudaGetSymbolAddress((void**)&hdb8,  g_hdb8);
    cudaGetSymbolAddress((void**)&kl,    g_kl);
    cudaGetSymbolAddress((void**)&lp,    g_lp);
    cudaGetSymbolAddress((void**)&We1t8, g_We1t8);
    cudaGetSymbolAddress((void**)&Wmlt,  g_Wmlt);
    cudaGetSymbolAddress((void**)&Wd1t,  g_Wd1t);
    cudaGetSymbolAddress((void**)&Wd2t8, g_Wd2t8);
    cudaGetSymbolAddress((void**)&bml,   g_bml);

    constexpr int SM_SMALL = GemmCfg<128,128>::SMEM;   // 3 x 32KB + pad
    constexpr int SM_BIG   = GemmCfg<128,256>::SMEM;   // 3 x 48KB + pad

    cudaFuncSetAttribute((const void*)mma_gemm<0,true ,128,128,128,2>, cudaFuncAttributeMaxDynamicSharedMemorySize, SM_SMALL);
    cudaFuncSetAttribute((const void*)mma_gemm<2,true ,128,128,128,2>, cudaFuncAttributeMaxDynamicSharedMemorySize, SM_SMALL);
    cudaFuncSetAttribute((const void*)mma_gemm<3,false,128,256,256,1>, cudaFuncAttributeMaxDynamicSharedMemorySize, SM_BIG);

    // 0) fused prep
    prep_kernel<<<18817, 256>>>(x, We1, Wmu, Wls, Wd1, Wd2, bmu, bls,
                                xb8, We1t8, Wmlt, Wd1t, Wd2t8, bml);
    // 1) h = relu((x@We1_fp8)/64 + be1) -> bf16     [FP8 tensor path]
    mma_gemm<0,true,128,128,128,2><<<dim3(8, 256), 128, SM_SMALL>>>(
        xb8, D_IN, We1t8, be1, 1.f / W_SCALE, hb, D_H,
        nullptr, nullptr, nullptr, nullptr, nullptr, nullptr, D_IN);
    // 2) [mu|ls] bf16 GEMM + fused reparam/KL + hd = relu(z@Wd1+bd1)*16 -> e4m3
    mma_gemm<3,false,128,256,256,1><<<dim3(1, 256), 256, SM_BIG>>>(
        hb, D_H, Wmlt, bml, 1.f, nullptr, 0, nullptr, kl, eps,
        Wd1t, bd1, hdb8, D_H);
    // 3) Bernoulli log-lik partials: logits = (hd_fp8@Wd2_fp8)/(16*64) + bd2
    mma_gemm<2,true,128,128,128,2><<<dim3(8, 256), 128, SM_SMALL>>>(
        hdb8, D_H, Wd2t8, bd2, 1.f / (W_SCALE * HD_SCALE), nullptr, 0,
        xb8, lp, nullptr, nullptr, nullptr, nullptr, D_H);
    // 4) out = log_px - kl
    finalize_kernel<<<BATCH / 256, 256>>>(kl, lp, out);
}

// round 11
// speedup vs baseline: 1.2643x; 1.2643x over previous
#include <cuda_runtime.h>
#include <cuda_bf16.h>
#include <cstdint>
#include <math.h>

#define BATCH 32768
#define D_IN  1024
#define D_H   1024
#define D_L   128

// ---------------- scratch (__device__ globals; alloc-free rule) -------------
__device__ __align__(16) __nv_bfloat16 g_xb [BATCH * D_IN];
__device__ __align__(16) __nv_bfloat16 g_hb [BATCH * D_H];
__device__ __align__(16) __nv_bfloat16 g_hdb[BATCH * D_H];
__device__ __align__(16) float         g_kl [BATCH];
__device__ __align__(16) float         g_lp [BATCH * 16];
__device__ __align__(16) __nv_bfloat16 g_We1t[D_H * D_IN];     // [N][K] K-major
__device__ __align__(16) __nv_bfloat16 g_Wmlt[256 * D_H];
__device__ __align__(16) __nv_bfloat16 g_Wd1t[D_H * D_L];
__device__ __align__(16) __nv_bfloat16 g_Wd2t[D_IN * D_H];
__device__ __align__(16) float         g_bml [256];

// ---------------- helpers ----------------------------------------------------
__device__ __forceinline__ uint32_t smem_u32(const void* p) {
    uint32_t a;
    asm("{ .reg .u64 t; cvta.to.shared.u64 t, %1; cvt.u32.u64 %0, t; }" : "=r"(a) : "l"(p));
    return a;
}

#define CP_ASYNC16(dst, src) \
    asm volatile("cp.async.cg.shared.global [%0], [%1], 16;" :: "r"(dst), "l"(src))
#define CP_COMMIT() asm volatile("cp.async.commit_group;" ::: "memory")
#define CP_WAIT0()  asm volatile("cp.async.wait_group 0;" ::: "memory")
#define CP_WAIT1()  asm volatile("cp.async.wait_group 1;" ::: "memory")

__device__ __forceinline__ void ldsm4(uint32_t& r0, uint32_t& r1, uint32_t& r2, uint32_t& r3,
                                      uint32_t addr) {
    asm volatile("ldmatrix.sync.aligned.m8n8.x4.shared.b16 {%0,%1,%2,%3}, [%4];"
                 : "=r"(r0), "=r"(r1), "=r"(r2), "=r"(r3) : "r"(addr));
}

__device__ __forceinline__ void mma16816(float* c, const uint32_t* a, const uint32_t* b) {
    asm volatile("mma.sync.aligned.m16n8k16.row.col.f32.bf16.bf16.f32 "
                 "{%0,%1,%2,%3}, {%4,%5,%6,%7}, {%8,%9}, {%0,%1,%2,%3};"
                 : "+f"(c[0]), "+f"(c[1]), "+f"(c[2]), "+f"(c[3])
                 : "r"(a[0]), "r"(a[1]), "r"(a[2]), "r"(a[3]), "r"(b[0]), "r"(b[1]));
}

// ---------------- HMMA GEMM: C[M,N] = A[M,K] @ Bt[N,K]^T (+epilogue) ---------
// Warp tile 64x64. Fragments double-buffered across kk (ldsm for kk+1 issued
// before kk's 32 HMMAs -> ldsm latency hidden under MMA issue).
// EPI 0/2: BM=BN=128, NTHR=128 (4 warps), MINB=2 (2 CTA/SM).
// EPI 3:   BM=128, BN=256, NTHR=256 (8 warps), MINB=1,
//          fused reparam + KL + hd = relu(z @ W2^T + B2) -> C2.
// 3-stage cp.async pipeline, ONE __syncthreads per K-chunk of 64.
static constexpr int NSTAGE = 3;

template<int BM, int BN> struct GemmCfg {
    static constexpr int STAGE = (BM + BN) * 64 * 2;
    static constexpr int SMEM  = NSTAGE * STAGE + 128;
};

template<int EPI, int BM, int BN, int NTHR, int MINB>
__global__ __launch_bounds__(NTHR, MINB)
void mma_gemm(const __nv_bfloat16* __restrict__ A, int lda,
              const __nv_bfloat16* __restrict__ Bt,
              const float* __restrict__ bias,
              void* __restrict__ Cv, int ldc,
              const __nv_bfloat16* __restrict__ XB,
              float* __restrict__ LP,
              const float* __restrict__ EPS,
              const __nv_bfloat16* __restrict__ W2,
              const float* __restrict__ B2,
              __nv_bfloat16* __restrict__ C2, int K)
{
    extern __shared__ char smraw[];
    uint32_t raw = smem_u32(smraw);
    uint32_t sbase = (raw + 127u) & ~127u;
    char* sm = smraw + (sbase - raw);

    constexpr int NWARP = NTHR / 32;
    constexpr int WM  = 2;
    constexpr int WNG = NWARP / WM;
    constexpr int WTN = BN / WNG;              // 64
    constexpr int NT  = WTN / 8;               // 8
    constexpr int A_BYTES = BM * 64 * 2;
    constexpr int STAGE_BYTES = GemmCfg<BM, BN>::STAGE;
    constexpr int AI = BM * 8 / NTHR, BI = BN * 8 / NTHR;

    const int tid  = threadIdx.x, lane = tid & 31, wid = tid >> 5;
    const int wm   = wid % WM, wn = wid / WM;
    const int bn   = blockIdx.x;
    const int m0   = blockIdx.y * BM, col0 = bn * BN;

    const __nv_bfloat16* Ag = A  + (size_t)m0   * lda;
    const __nv_bfloat16* Bg = Bt + (size_t)col0 * K;

    const int T = K >> 6;
    const int P = (T < NSTAGE - 1) ? T : (NSTAGE - 1);

    float acc[4][NT][4];
#pragma unroll
    for (int mt = 0; mt < 4; ++mt)
#pragma unroll
        for (int nt = 0; nt < NT; ++nt)
#pragma unroll
            for (int q = 0; q < 4; ++q) acc[mt][nt][q] = 0.f;

    auto issue_stage = [&](int kt) {
        uint32_t sA = sbase + (uint32_t)(kt % NSTAGE) * STAGE_BYTES;
        uint32_t sB = sA + A_BYTES;
        const __nv_bfloat16* Ak = Ag + kt * 64;
        const __nv_bfloat16* Bk = Bg + kt * 64;
#pragma unroll
        for (int i = 0; i < AI; ++i) {
            int idx = tid + i * NTHR;
            int rr = idx >> 3, cc = idx & 7;
            uint32_t sw = (uint32_t)(rr * 128 + ((cc ^ (rr & 7)) << 4));
            CP_ASYNC16(sA + sw, Ak + (size_t)rr * lda + cc * 8);
        }
#pragma unroll
        for (int i = 0; i < BI; ++i) {
            int idx = tid + i * NTHR;
            int rr = idx >> 3, cc = idx & 7;
            uint32_t sw = (uint32_t)(rr * 128 + ((cc ^ (rr & 7)) << 4));
            CP_ASYNC16(sB + sw, Bk + (size_t)rr * K + cc * 8);
        }
        CP_COMMIT();
    };

    for (int kt = 0; kt < P; ++kt) issue_stage(kt);
    int committed = P;

    const int g = lane >> 3, lq = lane & 7;

    // per-thread invariant ldsm base addresses (stage-relative)
    uint32_t aBase[4], bBase[4];
#pragma unroll
    for (int mt = 0; mt < 4; ++mt) {
        int row = wm * 64 + mt * 16 + (g & 1) * 8 + lq;
        aBase[mt] = (uint32_t)(row * 128 + (((g >> 1) ^ (row & 7)) << 4));
    }
#pragma unroll
    for (int p = 0; p < 4; ++p) {
        int row = wn * WTN + (p * 2 + (g >> 1)) * 8 + lq;
        bBase[p] = (uint32_t)(row * 128 + (((g & 1) ^ (row & 7)) << 4));
    }

    uint32_t af[2][4][4], bf[2][NT][2];

    for (int t = 0; t < T; ++t) {
        int allow = committed - t - 1;
        if (allow >= 1) { CP_WAIT1(); } else { CP_WAIT0(); }
        __syncthreads();

        if (t + NSTAGE - 1 < T) { issue_stage(t + NSTAGE - 1); committed++; }

        uint32_t sA = sbase + (uint32_t)(t % NSTAGE) * STAGE_BYTES;
        uint32_t sB = sA + A_BYTES;

        // prime kk=0 fragments
#pragma unroll
        for (int mt = 0; mt < 4; ++mt)
            ldsm4(af[0][mt][0], af[0][mt][1], af[0][mt][2], af[0][mt][3],
                  sA + aBase[mt]);
#pragma unroll
        for (int p = 0; p < 4; ++p) {
            uint32_t r0, r1, r2, r3;
            ldsm4(r0, r1, r2, r3, sB + bBase[p]);
            bf[0][p * 2][0] = r0; bf[0][p * 2][1] = r1;
            bf[0][p * 2 + 1][0] = r2; bf[0][p * 2 + 1][1] = r3;
        }

#pragma unroll
        for (int kk = 0; kk < 4; ++kk) {
            const int cur = kk & 1, nxt = cur ^ 1;
            if (kk < 3) {
                // kc advances by 2 per kk; swizzle XOR bit is (kc^...)<<4 with
                // kc bit0 fixed per thread -> address delta is XOR of (kk+1)*2<<4
                uint32_t axor = (uint32_t)(((kk + 1) * 2) << 4);
#pragma unroll
                for (int mt = 0; mt < 4; ++mt)
                    ldsm4(af[nxt][mt][0], af[nxt][mt][1], af[nxt][mt][2], af[nxt][mt][3],
                          (sA + aBase[mt]) ^ axor);
#pragma unroll
                for (int p = 0; p < 4; ++p) {
                    uint32_t r0, r1, r2, r3;
                    ldsm4(r0, r1, r2, r3, (sB + bBase[p]) ^ axor);
                    bf[nxt][p * 2][0] = r0; bf[nxt][p * 2][1] = r1;
                    bf[nxt][p * 2 + 1][0] = r2; bf[nxt][p * 2 + 1][1] = r3;
                }
            }
#pragma unroll
            for (int mt = 0; mt < 4; ++mt)
#pragma unroll
                for (int nt = 0; nt < NT; ++nt)
                    mma16816(acc[mt][nt], af[cur][mt], bf[cur][nt]);
        }
    }

    // ---------------- epilogue ----------------
    const int rbase = m0 + wm * 64 + (lane >> 2);
    const int cq    = (lane & 3) * 2;

    if (EPI == 0) {
        __nv_bfloat16* C = (__nv_bfloat16*)Cv;
#pragma unroll
        for (int mt = 0; mt < 4; ++mt) {
            int r0 = rbase + mt * 16;
#pragma unroll
            for (int nt = 0; nt < NT; ++nt) {
                int col = col0 + wn * WTN + nt * 8 + cq;
                float b0 = __ldg(bias + col), b1 = __ldg(bias + col + 1);
                float v0 = fmaxf(acc[mt][nt][0] + b0, 0.f);
                float v1 = fmaxf(acc[mt][nt][1] + b1, 0.f);
                float v2 = fmaxf(acc[mt][nt][2] + b0, 0.f);
                float v3 = fmaxf(acc[mt][nt][3] + b1, 0.f);
                __nv_bfloat162 p0 = __float22bfloat162_rn(make_float2(v0, v1));
                __nv_bfloat162 p1 = __float22bfloat162_rn(make_float2(v2, v3));
                *(uint32_t*)(C + (size_t)r0 * ldc + col)       = *(uint32_t*)&p0;
                *(uint32_t*)(C + (size_t)(r0 + 8) * ldc + col) = *(uint32_t*)&p1;
            }
        }
    } else if (EPI == 2) {
#pragma unroll
        for (int mt = 0; mt < 4; ++mt) {
            int r0 = rbase + mt * 16;
            float s0 = 0.f, s1 = 0.f;
#pragma unroll
            for (int nt = 0; nt < NT; ++nt) {
                int col = col0 + wn * WTN + nt * 8 + cq;
                float b0 = __ldg(bias + col), b1 = __ldg(bias + col + 1);
                uint32_t xw0 = *(const uint32_t*)(XB + (size_t)r0 * D_IN + col);
                uint32_t xw1 = *(const uint32_t*)(XB + (size_t)(r0 + 8) * D_IN + col);
                __nv_bfloat162 xp0 = *(__nv_bfloat162*)&xw0;
                __nv_bfloat162 xp1 = *(__nv_bfloat162*)&xw1;
                float a0 = acc[mt][nt][0] + b0, a1 = acc[mt][nt][1] + b1;
                float a2 = acc[mt][nt][2] + b0, a3 = acc[mt][nt][3] + b1;
                float t0 = (__bfloat162float(xp0.x) > 0.5f) ? -a0 : a0;
                float t1 = (__bfloat162float(xp0.y) > 0.5f) ? -a1 : a1;
                float t2 = (__bfloat162float(xp1.x) > 0.5f) ? -a2 : a2;
                float t3 = (__bfloat162float(xp1.y) > 0.5f) ? -a3 : a3;
                s0 += fmaxf(t0, 0.f) + log1pf(__expf(-fabsf(t0)));
                s0 += fmaxf(t1, 0.f) + log1pf(__expf(-fabsf(t1)));
                s1 += fmaxf(t2, 0.f) + log1pf(__expf(-fabsf(t2)));
                s1 += fmaxf(t3, 0.f) + log1pf(__expf(-fabsf(t3)));
            }
            s0 += __shfl_xor_sync(0xffffffffu, s0, 1);
            s0 += __shfl_xor_sync(0xffffffffu, s0, 2);
            s1 += __shfl_xor_sync(0xffffffffu, s1, 1);
            s1 += __shfl_xor_sync(0xffffffffu, s1, 2);
            if ((lane & 3) == 0) {
                LP[(size_t)r0 * 16 + bn * 2 + wn]       = -s0;
                LP[(size_t)(r0 + 8) * 16 + bn * 2 + wn] = -s1;
            }
        }
    } else {
        // EPI 3: fused reparam + KL + hd GEMM. BM=128, BN=256 (mu|ls), NTHR=256.
        constexpr int SPAD = 258;
        float* S = (float*)sm;
        __syncthreads();
        const int rl = wm * 64 + (lane >> 2);
#pragma unroll
        for (int mt = 0; mt < 4; ++mt) {
            int r0 = rl + mt * 16;
#pragma unroll
            for (int nt = 0; nt < NT; ++nt) {
                int col = wn * WTN + nt * 8 + cq;
                float b0 = __ldg(bias + col), b1 = __ldg(bias + col + 1);
                *(float2*)&S[(size_t)r0 * SPAD + col] =
                    make_float2(acc[mt][nt][0] + b0, acc[mt][nt][1] + b1);
                *(float2*)&S[(size_t)(r0 + 8) * SPAD + col] =
                    make_float2(acc[mt][nt][2] + b0, acc[mt][nt][3] + b1);
            }
        }
        __syncthreads();

        const int r = tid >> 1, h = tid & 1;
        const size_t grow = (size_t)m0 + r;
        const float* erow = EPS + grow * 128 + h * 64;
        float kla = 0.f;
        uint32_t zbuf[32];
#pragma unroll
        for (int j = 0; j < 32; ++j) {
            int c = h * 64 + 2 * j;
            float mu0 = S[(size_t)r * SPAD + c];
            float mu1 = S[(size_t)r * SPAD + c + 1];
            float l0  = S[(size_t)r * SPAD + c + 128];
            float l1  = S[(size_t)r * SPAD + c + 129];
            float2 ep = *(const float2*)&erow[2 * j];
            float s0 = expf(l0), s1 = expf(l1);
            float z0 = fmaf(s0, ep.x, mu0), z1 = fmaf(s1, ep.y, mu1);
            __nv_bfloat162 p = __float22bfloat162_rn(make_float2(z0, z1));
            zbuf[j] = *(uint32_t*)&p;
            kla += s0 * s0 + mu0 * mu0 - 2.f * l0 - 1.f;
            kla += s1 * s1 + mu1 * mu1 - 2.f * l1 - 1.f;
        }
        kla += __shfl_xor_sync(0xffffffffu, kla, 1);
        if (h == 0) LP[grow] = 0.5f * kla;
        __syncthreads();

        // stage z into smem as two swizzled A-chunks (16KB each, at sbase)
#pragma unroll
        for (int cc = 0; cc < 8; ++cc) {
            uint32_t off = (uint32_t)h * 16384u +
                           (uint32_t)(r * 128 + ((cc ^ (r & 7)) << 4));
            *(int4*)(sm + off) = ((int4*)zbuf)[cc];
        }

        auto issue_b = [&](int nb) {
            uint32_t sB = sbase + 32768u + (uint32_t)(nb % 3) * 32768u;
            const __nv_bfloat16* Bk = W2 + (size_t)(nb * 128) * 128;
#pragma unroll
            for (int i = 0; i < 2048 / NTHR; ++i) {
                int idx = tid + i * NTHR;
                int tt = idx >> 10;
                int rr = (idx >> 3) & 127;
                int cc = idx & 7;
                uint32_t sw = (uint32_t)(rr * 128 + ((cc ^ (rr & 7)) << 4));
                CP_ASYNC16(sB + (uint32_t)tt * 16384u + sw,
                           Bk + (size_t)rr * 128 + tt * 64 + cc * 8);
            }
            CP_COMMIT();
        };
        issue_b(0); issue_b(1);

        for (int nb = 0; nb < 8; ++nb) {
            if (nb < 7) { CP_WAIT1(); } else { CP_WAIT0(); }
            __syncthreads();
            if (nb + 2 < 8) issue_b(nb + 2);

            uint32_t sB = sbase + 32768u + (uint32_t)(nb % 3) * 32768u;
            float acc2[4][4][4];
#pragma unroll
            for (int mt = 0; mt < 4; ++mt)
#pragma unroll
                for (int nt = 0; nt < 4; ++nt)
#pragma unroll
                    for (int q = 0; q < 4; ++q) acc2[mt][nt][q] = 0.f;

#pragma unroll
            for (int t = 0; t < 2; ++t) {
#pragma unroll
                for (int kk = 0; kk < 4; ++kk) {
                    uint32_t a[4][4];
#pragma unroll
                    for (int mt = 0; mt < 4; ++mt) {
                        int row = wm * 64 + mt * 16 + (g & 1) * 8 + lq;
                        int kc  = kk * 2 + (g >> 1);
                        uint32_t ad = sbase + (uint32_t)t * 16384u +
                                      (uint32_t)(row * 128 + ((kc ^ (row & 7)) << 4));
                        ldsm4(a[mt][0], a[mt][1], a[mt][2], a[mt][3], ad);
                    }
                    uint32_t b[4][2];
#pragma unroll
                    for (int p = 0; p < 2; ++p) {
                        int row = wn * 32 + (p * 2 + (g >> 1)) * 8 + lq;
                        int kc  = kk * 2 + (g & 1);
                        uint32_t ad = sB + (uint32_t)t * 16384u +
                                      (uint32_t)(row * 128 + ((kc ^ (row & 7)) << 4));
                        uint32_t r0, r1, r2, r3;
                        ldsm4(r0, r1, r2, r3, ad);
                        b[p * 2][0] = r0; b[p * 2][1] = r1;
                        b[p * 2 + 1][0] = r2; b[p * 2 + 1][1] = r3;
                    }
#pragma unroll
                    for (int mt = 0; mt < 4; ++mt)
#pragma unroll
                        for (int nt = 0; nt < 4; ++nt)
                            mma16816(acc2[mt][nt], a[mt], b[nt]);
                }
            }
#pragma unroll
            for (int mt = 0; mt < 4; ++mt) {
                int r0 = rbase + mt * 16;
#pragma unroll
                for (int nt = 0; nt < 4; ++nt) {
                    int col = nb * 128 + wn * 32 + nt * 8 + cq;
                    float b0 = __ldg(B2 + col), b1 = __ldg(B2 + col + 1);
                    float v0 = fmaxf(acc2[mt][nt][0] + b0, 0.f);
                    float v1 = fmaxf(acc2[mt][nt][1] + b1, 0.f);
                    float v2 = fmaxf(acc2[mt][nt][2] + b0, 0.f);
                    float v3 = fmaxf(acc2[mt][nt][3] + b1, 0.f);
                    __nv_bfloat162 p0 = __float22bfloat162_rn(make_float2(v0, v1));
                    __nv_bfloat162 p1 = __float22bfloat162_rn(make_float2(v2, v3));
                    *(uint32_t*)(C2 + (size_t)r0 * D_H + col)       = *(uint32_t*)&p0;
                    *(uint32_t*)(C2 + (size_t)(r0 + 8) * D_H + col) = *(uint32_t*)&p1;
                }
            }
        }
    }
}

// ---------------- fused prep kernel ------------------------------------------
__device__ __forceinline__ void do_transpose(float (*ts)[33],
                                             const float* __restrict__ in,
                                             __nv_bfloat16* __restrict__ out,
                                             int K, int N, int rowOff, int bx, int by, int tid) {
    int tx = tid & 31, ty = tid >> 5;
    int k0 = by * 32, n0 = bx * 32;
    for (int j = ty; j < 32; j += 8)
        ts[j][tx] = in[(size_t)(k0 + j) * N + n0 + tx];
    __syncthreads();
    for (int j = ty; j < 32; j += 8)
        out[(size_t)(rowOff + n0 + j) * K + k0 + tx] = __float2bfloat16(ts[tx][j]);
}

__global__ __launch_bounds__(256)
void prep_kernel(const float* __restrict__ x,
                 const float* __restrict__ We1, const float* __restrict__ Wmu,
                 const float* __restrict__ Wls, const float* __restrict__ Wd1,
                 const float* __restrict__ Wd2, const float* __restrict__ bmu,
                 const float* __restrict__ bls,
                 __nv_bfloat16* __restrict__ xb, __nv_bfloat16* __restrict__ We1t,
                 __nv_bfloat16* __restrict__ Wmlt, __nv_bfloat16* __restrict__ Wd1t,
                 __nv_bfloat16* __restrict__ Wd2t, float* __restrict__ bml)
{
    __shared__ float ts[32][33];
    const int b = blockIdx.x, tid = threadIdx.x;
    if (b < 16384) {
        size_t i = ((size_t)b * 256 + tid) * 8;
        float4 a = *(const float4*)(x + i);
        float4 c = *(const float4*)(x + i + 4);
        __nv_bfloat162 p[4];
        p[0] = __float22bfloat162_rn(make_float2(a.x, a.y));
        p[1] = __float22bfloat162_rn(make_float2(a.z, a.w));
        p[2] = __float22bfloat162_rn(make_float2(c.x, c.y));
        p[3] = __float22bfloat162_rn(make_float2(c.z, c.w));
        *(int4*)(xb + i) = *(int4*)p;
    } else if (b < 17408) {
        int r = b - 16384;  do_transpose(ts, We1, We1t, 1024, 1024, 0,   r % 32, r / 32, tid);
    } else if (b < 17536) {
        int r = b - 17408;  do_transpose(ts, Wmu, Wmlt, 1024, 128,  0,   r % 4,  r / 4,  tid);
    } else if (b < 17664) {
        int r = b - 17536;  do_transpose(ts, Wls, Wmlt, 1024, 128,  128, r % 4,  r / 4,  tid);
    } else if (b < 17792) {
        int r = b - 17664;  do_transpose(ts, Wd1, Wd1t, 128,  1024, 0,   r % 32, r / 32, tid);
    } else if (b < 18816) {
        int r = b - 17792;  do_transpose(ts, Wd2, Wd2t, 1024, 1024, 0,   r % 32, r / 32, tid);
    } else {
        bml[tid] = (tid < 128) ? bmu[tid] : bls[tid - 128];
    }
}

__global__ void finalize_kernel(const float* __restrict__ kl_, const float* __restrict__ lp_,
                                float* __restrict__ out) {
    int r = blockIdx.x * blockDim.x + threadIdx.x;
    float s = 0.f;
#pragma unroll
    for (int j = 0; j < 16; j++) s += lp_[(size_t)r * 16 + j];
    out[r] = s - kl_[r];
}

// ---------------- launch ------------------------------------------------------
extern "C" void kernel_launch(void* const* d_in, const int* in_sizes, int n_in,
                              void* d_out, int out_size)
{
    const float* x   = (const float*)d_in[0];
    const float* eps = (const float*)d_in[1];
    const float* We1 = (const float*)d_in[2];
    const float* be1 = (const float*)d_in[3];
    const float* Wmu = (const float*)d_in[4];
    const float* bmu = (const float*)d_in[5];
    const float* Wls = (const float*)d_in[6];
    const float* bls = (const float*)d_in[7];
    const float* Wd1 = (const float*)d_in[8];
    const float* bd1 = (const float*)d_in[9];
    const float* Wd2 = (const float*)d_in[10];
    const float* bd2 = (const float*)d_in[11];
    float* out = (float*)d_out;

    __nv_bfloat16 *xb, *hb, *hdb, *We1t, *Wmlt, *Wd1t, *Wd2t;
    float *kl, *lp, *bml;
    cudaGetSymbolAddress((void**)&xb,   g_xb);
    cudaGetSymbolAddress((void**)&hb,   g_hb);
    cudaGetSymbolAddress((void**)&hdb,  g_hdb);
    cudaGetSymbolAddress((void**)&kl,   g_kl);
    cudaGetSymbolAddress((void**)&lp,   g_lp);
    cudaGetSymbolAddress((void**)&We1t, g_We1t);
    cudaGetSymbolAddress((void**)&Wmlt, g_Wmlt);
    cudaGetSymbolAddress((void**)&Wd1t, g_Wd1t);
    cudaGetSymbolAddress((void**)&Wd2t, g_Wd2t);
    cudaGetSymbolAddress((void**)&bml,  g_bml);

    constexpr int SM_SMALL = GemmCfg<128,128>::SMEM;   // 3 x 32KB + pad
    constexpr int SM_BIG   = GemmCfg<128,256>::SMEM;   // 3 x 48KB + pad

    cudaFuncSetAttribute((const void*)mma_gemm<0,128,128,128,2>, cudaFuncAttributeMaxDynamicSharedMemorySize, SM_SMALL);
    cudaFuncSetAttribute((const void*)mma_gemm<2,128,128,128,2>, cudaFuncAttributeMaxDynamicSharedMemorySize, SM_SMALL);
    cudaFuncSetAttribute((const void*)mma_gemm<3,128,256,256,1>, cudaFuncAttributeMaxDynamicSharedMemorySize, SM_BIG);

    // 0) fused prep
    prep_kernel<<<18817, 256>>>(x, We1, Wmu, Wls, Wd1, Wd2, bmu, bls,
                                xb, We1t, Wmlt, Wd1t, Wd2t, bml);
    // 1) h = relu(x @ We1 + be1) -> bf16
    mma_gemm<0,128,128,128,2><<<dim3(8, 256), 128, SM_SMALL>>>(
        xb, D_IN, We1t, be1, hb, D_H, nullptr, nullptr, nullptr,
        nullptr, nullptr, nullptr, D_IN);
    // 2) [mu|ls] GEMM + fused reparam/KL + hd = relu(z @ Wd1 + bd1) -> hdb
    mma_gemm<3,128,256,256,1><<<dim3(1, 256), 256, SM_BIG>>>(
        hb, D_H, Wmlt, bml, nullptr, 0, nullptr, kl, eps,
        Wd1t, bd1, hdb, D_H);
    // 3) Bernoulli log-lik partials from hd @ Wd2 + bd2
    mma_gemm<2,128,128,128,2><<<dim3(8, 256), 128, SM_SMALL>>>(
        hdb, D_H, Wd2t, bd2, nullptr, 0, xb, lp, nullptr,
        nullptr, nullptr, nullptr, D_H);
    // 4) out = log_px - kl
    finalize_kernel<<<BATCH / 256, 256>>>(kl, lp, out);
}

// round 12
// speedup vs baseline: 1.3461x; 1.0647x over previous
#include <cuda_runtime.h>
#include <cuda_bf16.h>
#include <cstdint>
#include <math.h>

#define BATCH 32768
#define D_IN  1024
#define D_H   1024
#define D_L   128

// ---------------- scratch (__device__ globals; alloc-free rule) -------------
__device__ __align__(16) __nv_bfloat16 g_xb [BATCH * D_IN];
__device__ __align__(16) __nv_bfloat16 g_hb [BATCH * D_H];
__device__ __align__(16) __nv_bfloat16 g_hdb[BATCH * D_H];
__device__ __align__(16) float         g_kl [BATCH];
__device__ __align__(16) float         g_lp [BATCH * 16];
__device__ __align__(16) __nv_bfloat16 g_We1t[D_H * D_IN];     // [N][K] K-major
__device__ __align__(16) __nv_bfloat16 g_Wmlt[256 * D_H];
__device__ __align__(16) __nv_bfloat16 g_Wd1t[D_H * D_L];
__device__ __align__(16) __nv_bfloat16 g_Wd2t[D_IN * D_H];
__device__ __align__(16) float         g_bml [256];

// ---------------- helpers ----------------------------------------------------
__device__ __forceinline__ uint32_t smem_u32(const void* p) {
    uint32_t a;
    asm("{ .reg .u64 t; cvta.to.shared.u64 t, %1; cvt.u32.u64 %0, t; }" : "=r"(a) : "l"(p));
    return a;
}

#define CP_ASYNC16(dst, src) \
    asm volatile("cp.async.cg.shared.global [%0], [%1], 16;" :: "r"(dst), "l"(src))
#define CP_COMMIT() asm volatile("cp.async.commit_group;" ::: "memory")
#define CP_WAIT0()  asm volatile("cp.async.wait_group 0;" ::: "memory")
#define CP_WAIT1()  asm volatile("cp.async.wait_group 1;" ::: "memory")

__device__ __forceinline__ void ldsm4(uint32_t& r0, uint32_t& r1, uint32_t& r2, uint32_t& r3,
                                      uint32_t addr) {
    asm volatile("ldmatrix.sync.aligned.m8n8.x4.shared.b16 {%0,%1,%2,%3}, [%4];"
                 : "=r"(r0), "=r"(r1), "=r"(r2), "=r"(r3) : "r"(addr));
}

__device__ __forceinline__ void mma16816(float* c, const uint32_t* a, const uint32_t* b) {
    asm volatile("mma.sync.aligned.m16n8k16.row.col.f32.bf16.bf16.f32 "
                 "{%0,%1,%2,%3}, {%4,%5,%6,%7}, {%8,%9}, {%0,%1,%2,%3};"
                 : "+f"(c[0]), "+f"(c[1]), "+f"(c[2]), "+f"(c[3])
                 : "r"(a[0]), "r"(a[1]), "r"(a[2]), "r"(a[3]), "r"(b[0]), "r"(b[1]));
}

// fast softplus: max(t,0) + log(1+exp(-|t|)), MUFU-based
__device__ __forceinline__ float softplus_fast(float t) {
    return fmaxf(t, 0.f) + __logf(1.f + __expf(-fabsf(t)));
}

// ---------------- HMMA GEMM: C[M,N] = A[M,K] @ Bt[N,K]^T (+epilogue) ---------
// Warp tile 64x64. EPI 0/2: BM=BN=128, NTHR=128 (4 warps), MINB=2 (2 CTA/SM).
// EPI 3: BM=128, BN=256, NTHR=256 (8 warps), MINB=1,
//        fused reparam + KL + hd = relu(z @ W2^T + B2) -> C2.
// 3-stage cp.async pipeline, ONE __syncthreads per K-chunk of 64.
static constexpr int NSTAGE = 3;

template<int BM, int BN> struct GemmCfg {
    static constexpr int STAGE = (BM + BN) * 64 * 2;
    static constexpr int SMEM  = NSTAGE * STAGE + 128;
};

template<int EPI, int BM, int BN, int NTHR, int MINB>
__global__ __launch_bounds__(NTHR, MINB)
void mma_gemm(const __nv_bfloat16* __restrict__ A, int lda,
              const __nv_bfloat16* __restrict__ Bt,
              const float* __restrict__ bias,
              void* __restrict__ Cv, int ldc,
              const __nv_bfloat16* __restrict__ XB,
              float* __restrict__ LP,
              const float* __restrict__ EPS,
              const __nv_bfloat16* __restrict__ W2,
              const float* __restrict__ B2,
              __nv_bfloat16* __restrict__ C2, int K)
{
    extern __shared__ char smraw[];
    uint32_t raw = smem_u32(smraw);
    uint32_t sbase = (raw + 127u) & ~127u;
    char* sm = smraw + (sbase - raw);

    constexpr int NWARP = NTHR / 32;
    constexpr int WM  = 2;
    constexpr int WNG = NWARP / WM;
    constexpr int WTN = BN / WNG;              // 64
    constexpr int NT  = WTN / 8;               // 8
    constexpr int A_BYTES = BM * 64 * 2;
    constexpr int STAGE_BYTES = GemmCfg<BM, BN>::STAGE;
    constexpr int AI = BM * 8 / NTHR, BI = BN * 8 / NTHR;

    const int tid  = threadIdx.x, lane = tid & 31, wid = tid >> 5;
    const int wm   = wid % WM, wn = wid / WM;
    const int bn   = blockIdx.x;
    const int m0   = blockIdx.y * BM, col0 = bn * BN;

    const __nv_bfloat16* Ag = A  + (size_t)m0   * lda;
    const __nv_bfloat16* Bg = Bt + (size_t)col0 * K;

    const int T = K >> 6;
    const int P = (T < NSTAGE - 1) ? T : (NSTAGE - 1);

    float acc[4][NT][4];
#pragma unroll
    for (int mt = 0; mt < 4; ++mt)
#pragma unroll
        for (int nt = 0; nt < NT; ++nt)
#pragma unroll
            for (int q = 0; q < 4; ++q) acc[mt][nt][q] = 0.f;

    auto issue_stage = [&](int kt) {
        uint32_t sA = sbase + (uint32_t)(kt % NSTAGE) * STAGE_BYTES;
        uint32_t sB = sA + A_BYTES;
        const __nv_bfloat16* Ak = Ag + kt * 64;
        const __nv_bfloat16* Bk = Bg + kt * 64;
#pragma unroll
        for (int i = 0; i < AI; ++i) {
            int idx = tid + i * NTHR;
            int rr = idx >> 3, cc = idx & 7;
            uint32_t sw = (uint32_t)(rr * 128 + ((cc ^ (rr & 7)) << 4));
            CP_ASYNC16(sA + sw, Ak + (size_t)rr * lda + cc * 8);
        }
#pragma unroll
        for (int i = 0; i < BI; ++i) {
            int idx = tid + i * NTHR;
            int rr = idx >> 3, cc = idx & 7;
            uint32_t sw = (uint32_t)(rr * 128 + ((cc ^ (rr & 7)) << 4));
            CP_ASYNC16(sB + sw, Bk + (size_t)rr * K + cc * 8);
        }
        CP_COMMIT();
    };

    for (int kt = 0; kt < P; ++kt) issue_stage(kt);
    int committed = P;

    const int g = lane >> 3, lq = lane & 7;

    for (int t = 0; t < T; ++t) {
        int allow = committed - t - 1;
        if (allow >= 1) { CP_WAIT1(); } else { CP_WAIT0(); }
        __syncthreads();

        if (t + NSTAGE - 1 < T) { issue_stage(t + NSTAGE - 1); committed++; }

        uint32_t sA = sbase + (uint32_t)(t % NSTAGE) * STAGE_BYTES;
        uint32_t sB = sA + A_BYTES;

#pragma unroll
        for (int kk = 0; kk < 4; ++kk) {
            uint32_t a[4][4];
#pragma unroll
            for (int mt = 0; mt < 4; ++mt) {
                int row = wm * 64 + mt * 16 + (g & 1) * 8 + lq;
                int kc  = kk * 2 + (g >> 1);
                uint32_t ad = sA + (uint32_t)(row * 128 + ((kc ^ (row & 7)) << 4));
                ldsm4(a[mt][0], a[mt][1], a[mt][2], a[mt][3], ad);
            }
            uint32_t b[NT][2];
#pragma unroll
            for (int p = 0; p < 4; ++p) {
                int row = wn * WTN + (p * 2 + (g >> 1)) * 8 + lq;
                int kc  = kk * 2 + (g & 1);
                uint32_t ad = sB + (uint32_t)(row * 128 + ((kc ^ (row & 7)) << 4));
                uint32_t r0, r1, r2, r3;
                ldsm4(r0, r1, r2, r3, ad);
                b[p * 2][0] = r0; b[p * 2][1] = r1;
                b[p * 2 + 1][0] = r2; b[p * 2 + 1][1] = r3;
            }
#pragma unroll
            for (int mt = 0; mt < 4; ++mt)
#pragma unroll
                for (int nt = 0; nt < NT; ++nt)
                    mma16816(acc[mt][nt], a[mt], b[nt]);
        }
    }

    // ---------------- epilogue ----------------
    const int rbase = m0 + wm * 64 + (lane >> 2);
    const int cq    = (lane & 3) * 2;

    // hoist per-thread bias values (same for all mt)
    float bv[2 * NT];
#pragma unroll
    for (int nt = 0; nt < NT; ++nt) {
        int col = (EPI == 3 ? 0 : col0) + wn * WTN + nt * 8 + cq;
        bv[2 * nt]     = __ldg(bias + col);
        bv[2 * nt + 1] = __ldg(bias + col + 1);
    }

    if (EPI == 0) {
        __nv_bfloat16* C = (__nv_bfloat16*)Cv;
#pragma unroll
        for (int mt = 0; mt < 4; ++mt) {
            int r0 = rbase + mt * 16;
#pragma unroll
            for (int nt = 0; nt < NT; ++nt) {
                int col = col0 + wn * WTN + nt * 8 + cq;
                float v0 = fmaxf(acc[mt][nt][0] + bv[2*nt],   0.f);
                float v1 = fmaxf(acc[mt][nt][1] + bv[2*nt+1], 0.f);
                float v2 = fmaxf(acc[mt][nt][2] + bv[2*nt],   0.f);
                float v3 = fmaxf(acc[mt][nt][3] + bv[2*nt+1], 0.f);
                __nv_bfloat162 p0 = __float22bfloat162_rn(make_float2(v0, v1));
                __nv_bfloat162 p1 = __float22bfloat162_rn(make_float2(v2, v3));
                *(uint32_t*)(C + (size_t)r0 * ldc + col)       = *(uint32_t*)&p0;
                *(uint32_t*)(C + (size_t)(r0 + 8) * ldc + col) = *(uint32_t*)&p1;
            }
        }
    } else if (EPI == 2) {
#pragma unroll
        for (int mt = 0; mt < 4; ++mt) {
            int r0 = rbase + mt * 16;
            float s0 = 0.f, s1 = 0.f;
#pragma unroll
            for (int nt = 0; nt < NT; ++nt) {
                int col = col0 + wn * WTN + nt * 8 + cq;
                uint32_t xw0 = *(const uint32_t*)(XB + (size_t)r0 * D_IN + col);
                uint32_t xw1 = *(const uint32_t*)(XB + (size_t)(r0 + 8) * D_IN + col);
                __nv_bfloat162 xp0 = *(__nv_bfloat162*)&xw0;
                __nv_bfloat162 xp1 = *(__nv_bfloat162*)&xw1;
                float a0 = acc[mt][nt][0] + bv[2*nt];
                float a1 = acc[mt][nt][1] + bv[2*nt+1];
                float a2 = acc[mt][nt][2] + bv[2*nt];
                float a3 = acc[mt][nt][3] + bv[2*nt+1];
                float t0 = (__bfloat162float(xp0.x) > 0.5f) ? -a0 : a0;
                float t1 = (__bfloat162float(xp0.y) > 0.5f) ? -a1 : a1;
                float t2 = (__bfloat162float(xp1.x) > 0.5f) ? -a2 : a2;
                float t3 = (__bfloat162float(xp1.y) > 0.5f) ? -a3 : a3;
                s0 += softplus_fast(t0) + softplus_fast(t1);
                s1 += softplus_fast(t2) + softplus_fast(t3);
            }
            s0 += __shfl_xor_sync(0xffffffffu, s0, 1);
            s0 += __shfl_xor_sync(0xffffffffu, s0, 2);
            s1 += __shfl_xor_sync(0xffffffffu, s1, 1);
            s1 += __shfl_xor_sync(0xffffffffu, s1, 2);
            if ((lane & 3) == 0) {
                LP[(size_t)r0 * 16 + bn * 2 + wn]       = -s0;
                LP[(size_t)(r0 + 8) * 16 + bn * 2 + wn] = -s1;
            }
        }
    } else {
        // EPI 3: fused reparam + KL + hd GEMM. BM=128, BN=256 (mu|ls), NTHR=256.
        constexpr int SPAD = 258;
        float* S = (float*)sm;
        __syncthreads();
        const int rl = wm * 64 + (lane >> 2);
#pragma unroll
        for (int mt = 0; mt < 4; ++mt) {
            int r0 = rl + mt * 16;
#pragma unroll
            for (int nt = 0; nt < NT; ++nt) {
                int col = wn * WTN + nt * 8 + cq;
                *(float2*)&S[(size_t)r0 * SPAD + col] =
                    make_float2(acc[mt][nt][0] + bv[2*nt], acc[mt][nt][1] + bv[2*nt+1]);
                *(float2*)&S[(size_t)(r0 + 8) * SPAD + col] =
                    make_float2(acc[mt][nt][2] + bv[2*nt], acc[mt][nt][3] + bv[2*nt+1]);
            }
        }
        __syncthreads();

        const int r = tid >> 1, h = tid & 1;
        const size_t grow = (size_t)m0 + r;
        const float* erow = EPS + grow * 128 + h * 64;
        float kla = 0.f;
        uint32_t zbuf[32];
#pragma unroll
        for (int j = 0; j < 32; ++j) {
            int c = h * 64 + 2 * j;
            float mu0 = S[(size_t)r * SPAD + c];
            float mu1 = S[(size_t)r * SPAD + c + 1];
            float l0  = S[(size_t)r * SPAD + c + 128];
            float l1  = S[(size_t)r * SPAD + c + 129];
            float2 ep = *(const float2*)&erow[2 * j];
            float s0 = __expf(l0), s1 = __expf(l1);
            float z0 = fmaf(s0, ep.x, mu0), z1 = fmaf(s1, ep.y, mu1);
            __nv_bfloat162 p = __float22bfloat162_rn(make_float2(z0, z1));
            zbuf[j] = *(uint32_t*)&p;
            kla += s0 * s0 + mu0 * mu0 - 2.f * l0 - 1.f;
            kla += s1 * s1 + mu1 * mu1 - 2.f * l1 - 1.f;
        }
        kla += __shfl_xor_sync(0xffffffffu, kla, 1);
        if (h == 0) LP[grow] = 0.5f * kla;
        __syncthreads();

        // stage z into smem as two swizzled A-chunks (16KB each, at sbase)
#pragma unroll
        for (int cc = 0; cc < 8; ++cc) {
            uint32_t off = (uint32_t)h * 16384u +
                           (uint32_t)(r * 128 + ((cc ^ (r & 7)) << 4));
            *(int4*)(sm + off) = ((int4*)zbuf)[cc];
        }

        auto issue_b = [&](int nb) {
            uint32_t sB = sbase + 32768u + (uint32_t)(nb % 3) * 32768u;
            const __nv_bfloat16* Bk = W2 + (size_t)(nb * 128) * 128;
#pragma unroll
            for (int i = 0; i < 2048 / NTHR; ++i) {
                int idx = tid + i * NTHR;
                int tt = idx >> 10;
                int rr = (idx >> 3) & 127;
                int cc = idx & 7;
                uint32_t sw = (uint32_t)(rr * 128 + ((cc ^ (rr & 7)) << 4));
                CP_ASYNC16(sB + (uint32_t)tt * 16384u + sw,
                           Bk + (size_t)rr * 128 + tt * 64 + cc * 8);
            }
            CP_COMMIT();
        };
        issue_b(0); issue_b(1);

        for (int nb = 0; nb < 8; ++nb) {
            if (nb < 7) { CP_WAIT1(); } else { CP_WAIT0(); }
            __syncthreads();
            if (nb + 2 < 8) issue_b(nb + 2);

            uint32_t sB = sbase + 32768u + (uint32_t)(nb % 3) * 32768u;
            float acc2[4][4][4];
#pragma unroll
            for (int mt = 0; mt < 4; ++mt)
#pragma unroll
                for (int nt = 0; nt < 4; ++nt)
#pragma unroll
                    for (int q = 0; q < 4; ++q) acc2[mt][nt][q] = 0.f;

#pragma unroll
            for (int t = 0; t < 2; ++t) {
#pragma unroll
                for (int kk = 0; kk < 4; ++kk) {
                    uint32_t a[4][4];
#pragma unroll
                    for (int mt = 0; mt < 4; ++mt) {
                        int row = wm * 64 + mt * 16 + (g & 1) * 8 + lq;
                        int kc  = kk * 2 + (g >> 1);
                        uint32_t ad = sbase + (uint32_t)t * 16384u +
                                      (uint32_t)(row * 128 + ((kc ^ (row & 7)) << 4));
                        ldsm4(a[mt][0], a[mt][1], a[mt][2], a[mt][3], ad);
                    }
                    uint32_t b[4][2];
#pragma unroll
                    for (int p = 0; p < 2; ++p) {
                        int row = wn * 32 + (p * 2 + (g >> 1)) * 8 + lq;
                        int kc  = kk * 2 + (g & 1);
                        uint32_t ad = sB + (uint32_t)t * 16384u +
                                      (uint32_t)(row * 128 + ((kc ^ (row & 7)) << 4));
                        uint32_t r0, r1, r2, r3;
                        ldsm4(r0, r1, r2, r3, ad);
                        b[p * 2][0] = r0; b[p * 2][1] = r1;
                        b[p * 2 + 1][0] = r2; b[p * 2 + 1][1] = r3;
                    }
#pragma unroll
                    for (int mt = 0; mt < 4; ++mt)
#pragma unroll
                        for (int nt = 0; nt < 4; ++nt)
                            mma16816(acc2[mt][nt], a[mt], b[nt]);
                }
            }
#pragma unroll
            for (int mt = 0; mt < 4; ++mt) {
                int r0 = rbase + mt * 16;
#pragma unroll
                for (int nt = 0; nt < 4; ++nt) {
                    int col = nb * 128 + wn * 32 + nt * 8 + cq;
                    float b0 = __ldg(B2 + col), b1 = __ldg(B2 + col + 1);
                    float v0 = fmaxf(acc2[mt][nt][0] + b0, 0.f);
                    float v1 = fmaxf(acc2[mt][nt][1] + b1, 0.f);
                    float v2 = fmaxf(acc2[mt][nt][2] + b0, 0.f);
                    float v3 = fmaxf(acc2[mt][nt][3] + b1, 0.f);
                    __nv_bfloat162 p0 = __float22bfloat162_rn(make_float2(v0, v1));
                    __nv_bfloat162 p1 = __float22bfloat162_rn(make_float2(v2, v3));
                    *(uint32_t*)(C2 + (size_t)r0 * D_H + col)       = *(uint32_t*)&p0;
                    *(uint32_t*)(C2 + (size_t)(r0 + 8) * D_H + col) = *(uint32_t*)&p1;
                }
            }
        }
    }
}

// ---------------- fused prep kernel ------------------------------------------
__device__ __forceinline__ void do_transpose(float (*ts)[33],
                                             const float* __restrict__ in,
                                             __nv_bfloat16* __restrict__ out,
                                             int K, int N, int rowOff, int bx, int by, int tid) {
    int tx = tid & 31, ty = tid >> 5;
    int k0 = by * 32, n0 = bx * 32;
    for (int j = ty; j < 32; j += 8)
        ts[j][tx] = in[(size_t)(k0 + j) * N + n0 + tx];
    __syncthreads();
    for (int j = ty; j < 32; j += 8)
        out[(size_t)(rowOff + n0 + j) * K + k0 + tx] = __float2bfloat16(ts[tx][j]);
}

__global__ __launch_bounds__(256)
void prep_kernel(const float* __restrict__ x,
                 const float* __restrict__ We1, const float* __restrict__ Wmu,
                 const float* __restrict__ Wls, const float* __restrict__ Wd1,
                 const float* __restrict__ Wd2, const float* __restrict__ bmu,
                 const float* __restrict__ bls,
                 __nv_bfloat16* __restrict__ xb, __nv_bfloat16* __restrict__ We1t,
                 __nv_bfloat16* __restrict__ Wmlt, __nv_bfloat16* __restrict__ Wd1t,
                 __nv_bfloat16* __restrict__ Wd2t, float* __restrict__ bml)
{
    __shared__ float ts[32][33];
    const int b = blockIdx.x, tid = threadIdx.x;
    if (b < 16384) {
        size_t i = ((size_t)b * 256 + tid) * 8;
        float4 a = *(const float4*)(x + i);
        float4 c = *(const float4*)(x + i + 4);
        __nv_bfloat162 p[4];
        p[0] = __float22bfloat162_rn(make_float2(a.x, a.y));
        p[1] = __float22bfloat162_rn(make_float2(a.z, a.w));
        p[2] = __float22bfloat162_rn(make_float2(c.x, c.y));
        p[3] = __float22bfloat162_rn(make_float2(c.z, c.w));
        *(int4*)(xb + i) = *(int4*)p;
    } else if (b < 17408) {
        int r = b - 16384;  do_transpose(ts, We1, We1t, 1024, 1024, 0,   r % 32, r / 32, tid);
    } else if (b < 17536) {
        int r = b - 17408;  do_transpose(ts, Wmu, Wmlt, 1024, 128,  0,   r % 4,  r / 4,  tid);
    } else if (b < 17664) {
        int r = b - 17536;  do_transpose(ts, Wls, Wmlt, 1024, 128,  128, r % 4,  r / 4,  tid);
    } else if (b < 17792) {
        int r = b - 17664;  do_transpose(ts, Wd1, Wd1t, 128,  1024, 0,   r % 32, r / 32, tid);
    } else if (b < 18816) {
        int r = b - 17792;  do_transpose(ts, Wd2, Wd2t, 1024, 1024, 0,   r % 32, r / 32, tid);
    } else {
        bml[tid] = (tid < 128) ? bmu[tid] : bls[tid - 128];
    }
}

__global__ void finalize_kernel(const float* __restrict__ kl_, const float* __restrict__ lp_,
                                float* __restrict__ out) {
    int r = blockIdx.x * blockDim.x + threadIdx.x;
    float s = 0.f;
#pragma unroll
    for (int j = 0; j < 16; j++) s += lp_[(size_t)r * 16 + j];
    out[r] = s - kl_[r];
}

// ---------------- launch ------------------------------------------------------
extern "C" void kernel_launch(void* const* d_in, const int* in_sizes, int n_in,
                              void* d_out, int out_size)
{
    const float* x   = (const float*)d_in[0];
    const float* eps = (const float*)d_in[1];
    const float* We1 = (const float*)d_in[2];
    const float* be1 = (const float*)d_in[3];
    const float* Wmu = (const float*)d_in[4];
    const float* bmu = (const float*)d_in[5];
    const float* Wls = (const float*)d_in[6];
    const float* bls = (const float*)d_in[7];
    const float* Wd1 = (const float*)d_in[8];
    const float* bd1 = (const float*)d_in[9];
    const float* Wd2 = (const float*)d_in[10];
    const float* bd2 = (const float*)d_in[11];
    float* out = (float*)d_out;

    __nv_bfloat16 *xb, *hb, *hdb, *We1t, *Wmlt, *Wd1t, *Wd2t;
    float *kl, *lp, *bml;
    cudaGetSymbolAddress((void**)&xb,   g_xb);
    cudaGetSymbolAddress((void**)&hb,   g_hb);
    cudaGetSymbolAddress((void**)&hdb,  g_hdb);
    cudaGetSymbolAddress((void**)&kl,   g_kl);
    cudaGetSymbolAddress((void**)&lp,   g_lp);
    cudaGetSymbolAddress((void**)&We1t, g_We1t);
    cudaGetSymbolAddress((void**)&Wmlt, g_Wmlt);
    cudaGetSymbolAddress((void**)&Wd1t, g_Wd1t);
    cudaGetSymbolAddress((void**)&Wd2t, g_Wd2t);
    cudaGetSymbolAddress((void**)&bml,  g_bml);

    constexpr int SM_SMALL = GemmCfg<128,128>::SMEM;   // 3 x 32KB + pad
    constexpr int SM_BIG   = GemmCfg<128,256>::SMEM;   // 3 x 48KB + pad

    cudaFuncSetAttribute((const void*)mma_gemm<0,128,128,128,2>, cudaFuncAttributeMaxDynamicSharedMemorySize, SM_SMALL);
    cudaFuncSetAttribute((const void*)mma_gemm<2,128,128,128,2>, cudaFuncAttributeMaxDynamicSharedMemorySize, SM_SMALL);
    cudaFuncSetAttribute((const void*)mma_gemm<3,128,256,256,1>, cudaFuncAttributeMaxDynamicSharedMemorySize, SM_BIG);

    // 0) fused prep
    prep_kernel<<<18817, 256>>>(x, We1, Wmu, Wls, Wd1, Wd2, bmu, bls,
                                xb, We1t, Wmlt, Wd1t, Wd2t, bml);
    // 1) h = relu(x @ We1 + be1) -> bf16
    mma_gemm<0,128,128,128,2><<<dim3(8, 256), 128, SM_SMALL>>>(
        xb, D_IN, We1t, be1, hb, D_H, nullptr, nullptr, nullptr,
        nullptr, nullptr, nullptr, D_IN);
    // 2) [mu|ls] GEMM + fused reparam/KL + hd = relu(z @ Wd1 + bd1) -> hdb
    mma_gemm<3,128,256,256,1><<<dim3(1, 256), 256, SM_BIG>>>(
        hb, D_H, Wmlt, bml, nullptr, 0, nullptr, kl, eps,
        Wd1t, bd1, hdb, D_H);
    // 3) Bernoulli log-lik partials from hd @ Wd2 + bd2
    mma_gemm<2,128,128,128,2><<<dim3(8, 256), 128, SM_SMALL>>>(
        hdb, D_H, Wd2t, bd2, nullptr, 0, xb, lp, nullptr,
        nullptr, nullptr, nullptr, D_H);
    // 4) out = log_px - kl
    finalize_kernel<<<BATCH / 256, 256>>>(kl, lp, out);
}

// round 13
// speedup vs baseline: 1.3500x; 1.0029x over previous
#include <cuda_runtime.h>
#include <cuda_bf16.h>
#include <cstdint>
#include <math.h>

#define BATCH 32768
#define D_IN  1024
#define D_H   1024
#define D_L   128

// ---------------- scratch (__device__ globals; alloc-free rule) -------------
__device__ __align__(16) __nv_bfloat16 g_xb [BATCH * D_IN];
__device__ __align__(16) __nv_bfloat16 g_hb [BATCH * D_H];
__device__ __align__(16) __nv_bfloat16 g_hdb[BATCH * D_H];
__device__ __align__(16) float         g_kl [BATCH];
__device__ __align__(16) float         g_lp [BATCH * 16];
__device__ __align__(16) __nv_bfloat16 g_We1t[D_H * D_IN];     // [N][K] K-major
__device__ __align__(16) __nv_bfloat16 g_Wmlt[256 * D_H];
__device__ __align__(16) __nv_bfloat16 g_Wd1t[D_H * D_L];
__device__ __align__(16) __nv_bfloat16 g_Wd2t[D_IN * D_H];
__device__ __align__(16) float         g_bml [256];

// ---------------- helpers ----------------------------------------------------
__device__ __forceinline__ uint32_t smem_u32(const void* p) {
    uint32_t a;
    asm("{ .reg .u64 t; cvta.to.shared.u64 t, %1; cvt.u32.u64 %0, t; }" : "=r"(a) : "l"(p));
    return a;
}

#define CP_ASYNC16(dst, src) \
    asm volatile("cp.async.cg.shared.global [%0], [%1], 16;" :: "r"(dst), "l"(src))
#define CP_COMMIT() asm volatile("cp.async.commit_group;" ::: "memory")
#define CP_WAIT0()  asm volatile("cp.async.wait_group 0;" ::: "memory")
#define CP_WAIT1()  asm volatile("cp.async.wait_group 1;" ::: "memory")

__device__ __forceinline__ void ldsm4(uint32_t& r0, uint32_t& r1, uint32_t& r2, uint32_t& r3,
                                      uint32_t addr) {
    asm volatile("ldmatrix.sync.aligned.m8n8.x4.shared.b16 {%0,%1,%2,%3}, [%4];"
                 : "=r"(r0), "=r"(r1), "=r"(r2), "=r"(r3) : "r"(addr));
}

__device__ __forceinline__ void mma16816(float* c, const uint32_t* a, const uint32_t* b) {
    asm volatile("mma.sync.aligned.m16n8k16.row.col.f32.bf16.bf16.f32 "
                 "{%0,%1,%2,%3}, {%4,%5,%6,%7}, {%8,%9}, {%0,%1,%2,%3};"
                 : "+f"(c[0]), "+f"(c[1]), "+f"(c[2]), "+f"(c[3])
                 : "r"(a[0]), "r"(a[1]), "r"(a[2]), "r"(a[3]), "r"(b[0]), "r"(b[1]));
}

// ---------------- HMMA GEMM: C[M,N] = A[M,K] @ Bt[N,K]^T (+epilogue) ---------
// Warp tile 64x64. EPI 0/2: BM=BN=128, NTHR=128 (4 warps), MINB=2 (2 CTA/SM).
// EPI 3: BM=128, BN=256, NTHR=256 (8 warps), MINB=1,
//        fused reparam + KL + hd = relu(z @ W2^T + B2) -> C2.
// 3-stage cp.async pipeline, ONE __syncthreads per K-chunk of 64.
static constexpr int NSTAGE = 3;

template<int BM, int BN> struct GemmCfg {
    static constexpr int STAGE = (BM + BN) * 64 * 2;
    static constexpr int SMEM  = NSTAGE * STAGE + 128;
};

template<int EPI, int BM, int BN, int NTHR, int MINB>
__global__ __launch_bounds__(NTHR, MINB)
void mma_gemm(const __nv_bfloat16* __restrict__ A, int lda,
              const __nv_bfloat16* __restrict__ Bt,
              const float* __restrict__ bias,
              void* __restrict__ Cv, int ldc,
              const __nv_bfloat16* __restrict__ XB,
              float* __restrict__ LP,
              const float* __restrict__ EPS,
              const __nv_bfloat16* __restrict__ W2,
              const float* __restrict__ B2,
              __nv_bfloat16* __restrict__ C2, int K)
{
    extern __shared__ char smraw[];
    uint32_t raw = smem_u32(smraw);
    uint32_t sbase = (raw + 127u) & ~127u;
    char* sm = smraw + (sbase - raw);

    constexpr int NWARP = NTHR / 32;
    constexpr int WM  = 2;
    constexpr int WNG = NWARP / WM;
    constexpr int WTN = BN / WNG;              // 64
    constexpr int NT  = WTN / 8;               // 8
    constexpr int A_BYTES = BM * 64 * 2;
    constexpr int STAGE_BYTES = GemmCfg<BM, BN>::STAGE;
    constexpr int AI = BM * 8 / NTHR, BI = BN * 8 / NTHR;

    const int tid  = threadIdx.x, lane = tid & 31, wid = tid >> 5;
    const int wm   = wid % WM, wn = wid / WM;
    const int bn   = blockIdx.x;
    const int m0   = blockIdx.y * BM, col0 = bn * BN;

    const __nv_bfloat16* Ag = A  + (size_t)m0   * lda;
    const __nv_bfloat16* Bg = Bt + (size_t)col0 * K;

    const int T = K >> 6;
    const int P = (T < NSTAGE - 1) ? T : (NSTAGE - 1);

    float acc[4][NT][4];
#pragma unroll
    for (int mt = 0; mt < 4; ++mt)
#pragma unroll
        for (int nt = 0; nt < NT; ++nt)
#pragma unroll
            for (int q = 0; q < 4; ++q) acc[mt][nt][q] = 0.f;

    auto issue_stage = [&](int kt) {
        uint32_t sA = sbase + (uint32_t)(kt % NSTAGE) * STAGE_BYTES;
        uint32_t sB = sA + A_BYTES;
        const __nv_bfloat16* Ak = Ag + kt * 64;
        const __nv_bfloat16* Bk = Bg + kt * 64;
#pragma unroll
        for (int i = 0; i < AI; ++i) {
            int idx = tid + i * NTHR;
            int rr = idx >> 3, cc = idx & 7;
            uint32_t sw = (uint32_t)(rr * 128 + ((cc ^ (rr & 7)) << 4));
            CP_ASYNC16(sA + sw, Ak + (size_t)rr * lda + cc * 8);
        }
#pragma unroll
        for (int i = 0; i < BI; ++i) {
            int idx = tid + i * NTHR;
            int rr = idx >> 3, cc = idx & 7;
            uint32_t sw = (uint32_t)(rr * 128 + ((cc ^ (rr & 7)) << 4));
            CP_ASYNC16(sB + sw, Bk + (size_t)rr * K + cc * 8);
        }
        CP_COMMIT();
    };

    for (int kt = 0; kt < P; ++kt) issue_stage(kt);
    int committed = P;

    const int g = lane >> 3, lq = lane & 7;

    // row&7 == lq for all ldsm rows -> per-kk swizzle offsets shared by all loads
    uint32_t aRow[4], bRow[4];
#pragma unroll
    for (int mt = 0; mt < 4; ++mt)
        aRow[mt] = (uint32_t)((wm * 64 + mt * 16 + (g & 1) * 8 + lq) * 128);
#pragma unroll
    for (int p = 0; p < 4; ++p)
        bRow[p] = (uint32_t)((wn * WTN + (p * 2 + (g >> 1)) * 8 + lq) * 128);

    for (int t = 0; t < T; ++t) {
        int allow = committed - t - 1;
        if (allow >= 1) { CP_WAIT1(); } else { CP_WAIT0(); }
        __syncthreads();

        if (t + NSTAGE - 1 < T) { issue_stage(t + NSTAGE - 1); committed++; }

        uint32_t sA = sbase + (uint32_t)(t % NSTAGE) * STAGE_BYTES;
        uint32_t sB = sA + A_BYTES;

#pragma unroll
        for (int kk = 0; kk < 4; ++kk) {
            const uint32_t aOff = (uint32_t)(((kk * 2 + (g >> 1)) ^ lq) << 4);
            const uint32_t bOff = (uint32_t)(((kk * 2 + (g & 1)) ^ lq) << 4);
            uint32_t a[4][4];
#pragma unroll
            for (int mt = 0; mt < 4; ++mt)
                ldsm4(a[mt][0], a[mt][1], a[mt][2], a[mt][3], sA + aRow[mt] + aOff);
            uint32_t b[NT][2];
#pragma unroll
            for (int p = 0; p < 4; ++p) {
                uint32_t r0, r1, r2, r3;
                ldsm4(r0, r1, r2, r3, sB + bRow[p] + bOff);
                b[p * 2][0] = r0; b[p * 2][1] = r1;
                b[p * 2 + 1][0] = r2; b[p * 2 + 1][1] = r3;
            }
#pragma unroll
            for (int mt = 0; mt < 4; ++mt)
#pragma unroll
                for (int nt = 0; nt < NT; ++nt)
                    mma16816(acc[mt][nt], a[mt], b[nt]);
        }
    }

    // ---------------- epilogue ----------------
    const int rbase = m0 + wm * 64 + (lane >> 2);
    const int cq    = (lane & 3) * 2;

    float bv[2 * NT];
#pragma unroll
    for (int nt = 0; nt < NT; ++nt) {
        int col = (EPI == 3 ? 0 : col0) + wn * WTN + nt * 8 + cq;
        bv[2 * nt]     = __ldg(bias + col);
        bv[2 * nt + 1] = __ldg(bias + col + 1);
    }

    if (EPI == 0) {
        __nv_bfloat16* C = (__nv_bfloat16*)Cv;
#pragma unroll
        for (int mt = 0; mt < 4; ++mt) {
            int r0 = rbase + mt * 16;
#pragma unroll
            for (int nt = 0; nt < NT; ++nt) {
                int col = col0 + wn * WTN + nt * 8 + cq;
                float v0 = fmaxf(acc[mt][nt][0] + bv[2*nt],   0.f);
                float v1 = fmaxf(acc[mt][nt][1] + bv[2*nt+1], 0.f);
                float v2 = fmaxf(acc[mt][nt][2] + bv[2*nt],   0.f);
                float v3 = fmaxf(acc[mt][nt][3] + bv[2*nt+1], 0.f);
                __nv_bfloat162 p0 = __float22bfloat162_rn(make_float2(v0, v1));
                __nv_bfloat162 p1 = __float22bfloat162_rn(make_float2(v2, v3));
                *(uint32_t*)(C + (size_t)r0 * ldc + col)       = *(uint32_t*)&p0;
                *(uint32_t*)(C + (size_t)(r0 + 8) * ldc + col) = *(uint32_t*)&p1;
            }
        }
    } else if (EPI == 2) {
        // Bernoulli log-lik: sum softplus(t) = sum max(t,0) + log(prod(1+exp(-|t|)))
        // grouped 4-wide: one __logf per 4 elements (prod <= 16, safe).
#pragma unroll
        for (int mt = 0; mt < 4; ++mt) {
            int r0 = rbase + mt * 16;
            float s0 = 0.f, s1 = 0.f;
#pragma unroll
            for (int nt = 0; nt < NT; nt += 2) {
                float t[8];
#pragma unroll
                for (int j = 0; j < 2; ++j) {
                    int ntj = nt + j;
                    int col = col0 + wn * WTN + ntj * 8 + cq;
                    uint32_t xw0 = *(const uint32_t*)(XB + (size_t)r0 * D_IN + col);
                    uint32_t xw1 = *(const uint32_t*)(XB + (size_t)(r0 + 8) * D_IN + col);
                    float a0 = acc[mt][ntj][0] + bv[2*ntj];
                    float a1 = acc[mt][ntj][1] + bv[2*ntj+1];
                    float a2 = acc[mt][ntj][2] + bv[2*ntj];
                    float a3 = acc[mt][ntj][3] + bv[2*ntj+1];
                    t[j*4+0] = (xw0 & 0x0000ffffu) ? -a0 : a0;
                    t[j*4+1] = (xw0 & 0xffff0000u) ? -a1 : a1;
                    t[j*4+2] = (xw1 & 0x0000ffffu) ? -a2 : a2;
                    t[j*4+3] = (xw1 & 0xffff0000u) ? -a3 : a3;
                }
                // s0 gets elems {0,1,4,5} (row r0), s1 gets {2,3,6,7} (row r0+8)
                float p0 = (1.f + __expf(-fabsf(t[0]))) * (1.f + __expf(-fabsf(t[1])));
                p0 *= (1.f + __expf(-fabsf(t[4]))) * (1.f + __expf(-fabsf(t[5])));
                float p1 = (1.f + __expf(-fabsf(t[2]))) * (1.f + __expf(-fabsf(t[3])));
                p1 *= (1.f + __expf(-fabsf(t[6]))) * (1.f + __expf(-fabsf(t[7])));
                s0 += fmaxf(t[0], 0.f) + fmaxf(t[1], 0.f) + fmaxf(t[4], 0.f) + fmaxf(t[5], 0.f)
                    + __logf(p0);
                s1 += fmaxf(t[2], 0.f) + fmaxf(t[3], 0.f) + fmaxf(t[6], 0.f) + fmaxf(t[7], 0.f)
                    + __logf(p1);
            }
            s0 += __shfl_xor_sync(0xffffffffu, s0, 1);
            s0 += __shfl_xor_sync(0xffffffffu, s0, 2);
            s1 += __shfl_xor_sync(0xffffffffu, s1, 1);
            s1 += __shfl_xor_sync(0xffffffffu, s1, 2);
            if ((lane & 3) == 0) {
                LP[(size_t)r0 * 16 + bn * 2 + wn]       = -s0;
                LP[(size_t)(r0 + 8) * 16 + bn * 2 + wn] = -s1;
            }
        }
    } else {
        // EPI 3: fused reparam + KL + hd GEMM. BM=128, BN=256 (mu|ls), NTHR=256.
        constexpr int SPAD = 258;
        float* S = (float*)sm;
        __syncthreads();
        const int rl = wm * 64 + (lane >> 2);
#pragma unroll
        for (int mt = 0; mt < 4; ++mt) {
            int r0 = rl + mt * 16;
#pragma unroll
            for (int nt = 0; nt < NT; ++nt) {
                int col = wn * WTN + nt * 8 + cq;
                *(float2*)&S[(size_t)r0 * SPAD + col] =
                    make_float2(acc[mt][nt][0] + bv[2*nt], acc[mt][nt][1] + bv[2*nt+1]);
                *(float2*)&S[(size_t)(r0 + 8) * SPAD + col] =
                    make_float2(acc[mt][nt][2] + bv[2*nt], acc[mt][nt][3] + bv[2*nt+1]);
            }
        }
        __syncthreads();

        const int r = tid >> 1, h = tid & 1;
        const size_t grow = (size_t)m0 + r;
        const float* erow = EPS + grow * 128 + h * 64;
        float kla = 0.f;
        uint32_t zbuf[32];
#pragma unroll
        for (int j = 0; j < 32; ++j) {
            int c = h * 64 + 2 * j;
            float mu0 = S[(size_t)r * SPAD + c];
            float mu1 = S[(size_t)r * SPAD + c + 1];
            float l0  = S[(size_t)r * SPAD + c + 128];
            float l1  = S[(size_t)r * SPAD + c + 129];
            float2 ep = *(const float2*)&erow[2 * j];
            float s0 = __expf(l0), s1 = __expf(l1);
            float z0 = fmaf(s0, ep.x, mu0), z1 = fmaf(s1, ep.y, mu1);
            __nv_bfloat162 p = __float22bfloat162_rn(make_float2(z0, z1));
            zbuf[j] = *(uint32_t*)&p;
            kla += s0 * s0 + mu0 * mu0 - 2.f * l0 - 1.f;
            kla += s1 * s1 + mu1 * mu1 - 2.f * l1 - 1.f;
        }
        kla += __shfl_xor_sync(0xffffffffu, kla, 1);
        if (h == 0) LP[grow] = 0.5f * kla;
        __syncthreads();

        // stage z into smem as two swizzled A-chunks (16KB each, at sbase)
#pragma unroll
        for (int cc = 0; cc < 8; ++cc) {
            uint32_t off = (uint32_t)h * 16384u +
                           (uint32_t)(r * 128 + ((cc ^ (r & 7)) << 4));
            *(int4*)(sm + off) = ((int4*)zbuf)[cc];
        }

        auto issue_b = [&](int nb) {
            uint32_t sB = sbase + 32768u + (uint32_t)(nb % 3) * 32768u;
            const __nv_bfloat16* Bk = W2 + (size_t)(nb * 128) * 128;
#pragma unroll
            for (int i = 0; i < 2048 / NTHR; ++i) {
                int idx = tid + i * NTHR;
                int tt = idx >> 10;
                int rr = (idx >> 3) & 127;
                int cc = idx & 7;
                uint32_t sw = (uint32_t)(rr * 128 + ((cc ^ (rr & 7)) << 4));
                CP_ASYNC16(sB + (uint32_t)tt * 16384u + sw,
                           Bk + (size_t)rr * 128 + tt * 64 + cc * 8);
            }
            CP_COMMIT();
        };
        issue_b(0); issue_b(1);

        for (int nb = 0; nb < 8; ++nb) {
            if (nb < 7) { CP_WAIT1(); } else { CP_WAIT0(); }
            __syncthreads();
            if (nb + 2 < 8) issue_b(nb + 2);

            uint32_t sB = sbase + 32768u + (uint32_t)(nb % 3) * 32768u;
            float acc2[4][4][4];
#pragma unroll
            for (int mt = 0; mt < 4; ++mt)
#pragma unroll
                for (int nt = 0; nt < 4; ++nt)
#pragma unroll
                    for (int q = 0; q < 4; ++q) acc2[mt][nt][q] = 0.f;

#pragma unroll
            for (int t = 0; t < 2; ++t) {
#pragma unroll
                for (int kk = 0; kk < 4; ++kk) {
                    uint32_t a[4][4];
#pragma unroll
                    for (int mt = 0; mt < 4; ++mt) {
                        int row = wm * 64 + mt * 16 + (g & 1) * 8 + lq;
                        int kc  = kk * 2 + (g >> 1);
                        uint32_t ad = sbase + (uint32_t)t * 16384u +
                                      (uint32_t)(row * 128 + ((kc ^ (row & 7)) << 4));
                        ldsm4(a[mt][0], a[mt][1], a[mt][2], a[mt][3], ad);
                    }
                    uint32_t b[4][2];
#pragma unroll
                    for (int p = 0; p < 2; ++p) {
                        int row = wn * 32 + (p * 2 + (g >> 1)) * 8 + lq;
                        int kc  = kk * 2 + (g & 1);
                        uint32_t ad = sB + (uint32_t)t * 16384u +
                                      (uint32_t)(row * 128 + ((kc ^ (row & 7)) << 4));
                        uint32_t r0, r1, r2, r3;
                        ldsm4(r0, r1, r2, r3, ad);
                        b[p * 2][0] = r0; b[p * 2][1] = r1;
                        b[p * 2 + 1][0] = r2; b[p * 2 + 1][1] = r3;
                    }
#pragma unroll
                    for (int mt = 0; mt < 4; ++mt)
#pragma unroll
                        for (int nt = 0; nt < 4; ++nt)
                            mma16816(acc2[mt][nt], a[mt], b[nt]);
                }
            }
#pragma unroll
            for (int mt = 0; mt < 4; ++mt) {
                int r0 = rbase + mt * 16;
#pragma unroll
                for (int nt = 0; nt < 4; ++nt) {
                    int col = nb * 128 + wn * 32 + nt * 8 + cq;
                    float b0 = __ldg(B2 + col), b1 = __ldg(B2 + col + 1);
                    float v0 = fmaxf(acc2[mt][nt][0] + b0, 0.f);
                    float v1 = fmaxf(acc2[mt][nt][1] + b1, 0.f);
                    float v2 = fmaxf(acc2[mt][nt][2] + b0, 0.f);
                    float v3 = fmaxf(acc2[mt][nt][3] + b1, 0.f);
                    __nv_bfloat162 p0 = __float22bfloat162_rn(make_float2(v0, v1));
                    __nv_bfloat162 p1 = __float22bfloat162_rn(make_float2(v2, v3));
                    *(uint32_t*)(C2 + (size_t)r0 * D_H + col)       = *(uint32_t*)&p0;
                    *(uint32_t*)(C2 + (size_t)(r0 + 8) * D_H + col) = *(uint32_t*)&p1;
                }
            }
        }
    }
}

// ---------------- fused prep kernel ------------------------------------------
__device__ __forceinline__ void do_transpose(float (*ts)[33],
                                             const float* __restrict__ in,
                                             __nv_bfloat16* __restrict__ out,
                                             int K, int N, int rowOff, int bx, int by, int tid) {
    int tx = tid & 31, ty = tid >> 5;
    int k0 = by * 32, n0 = bx * 32;
    for (int j = ty; j < 32; j += 8)
        ts[j][tx] = in[(size_t)(k0 + j) * N + n0 + tx];
    __syncthreads();
    for (int j = ty; j < 32; j += 8)
        out[(size_t)(rowOff + n0 + j) * K + k0 + tx] = __float2bfloat16(ts[tx][j]);
}

__global__ __launch_bounds__(256)
void prep_kernel(const float* __restrict__ x,
                 const float* __restrict__ We1, const float* __restrict__ Wmu,
                 const float* __restrict__ Wls, const float* __restrict__ Wd1,
                 const float* __restrict__ Wd2, const float* __restrict__ bmu,
                 const float* __restrict__ bls,
                 __nv_bfloat16* __restrict__ xb, __nv_bfloat16* __restrict__ We1t,
                 __nv_bfloat16* __restrict__ Wmlt, __nv_bfloat16* __restrict__ Wd1t,
                 __nv_bfloat16* __restrict__ Wd2t, float* __restrict__ bml)
{
    __shared__ float ts[32][33];
    const int b = blockIdx.x, tid = threadIdx.x;
    if (b < 16384) {
        size_t i = ((size_t)b * 256 + tid) * 8;
        float4 a = *(const float4*)(x + i);
        float4 c = *(const float4*)(x + i + 4);
        __nv_bfloat162 p[4];
        p[0] = __float22bfloat162_rn(make_float2(a.x, a.y));
        p[1] = __float22bfloat162_rn(make_float2(a.z, a.w));
        p[2] = __float22bfloat162_rn(make_float2(c.x, c.y));
        p[3] = __float22bfloat162_rn(make_float2(c.z, c.w));
        *(int4*)(xb + i) = *(int4*)p;
    } else if (b < 17408) {
        int r = b - 16384;  do_transpose(ts, We1, We1t, 1024, 1024, 0,   r % 32, r / 32, tid);
    } else if (b < 17536) {
        int r = b - 17408;  do_transpose(ts, Wmu, Wmlt, 1024, 128,  0,   r % 4,  r / 4,  tid);
    } else if (b < 17664) {
        int r = b - 17536;  do_transpose(ts, Wls, Wmlt, 1024, 128,  128, r % 4,  r / 4,  tid);
    } else if (b < 17792) {
        int r = b - 17664;  do_transpose(ts, Wd1, Wd1t, 128,  1024, 0,   r % 32, r / 32, tid);
    } else if (b < 18816) {
        int r = b - 17792;  do_transpose(ts, Wd2, Wd2t, 1024, 1024, 0,   r % 32, r / 32, tid);
    } else {
        bml[tid] = (tid < 128) ? bmu[tid] : bls[tid - 128];
    }
}

__global__ void finalize_kernel(const float* __restrict__ kl_, const float* __restrict__ lp_,
                                float* __restrict__ out) {
    int r = blockIdx.x * blockDim.x + threadIdx.x;
    float s = 0.f;
#pragma unroll
    for (int j = 0; j < 16; j++) s += lp_[(size_t)r * 16 + j];
    out[r] = s - kl_[r];
}

// ---------------- launch ------------------------------------------------------
extern "C" void kernel_launch(void* const* d_in, const int* in_sizes, int n_in,
                              void* d_out, int out_size)
{
    const float* x   = (const float*)d_in[0];
    const float* eps = (const float*)d_in[1];
    const float* We1 = (const float*)d_in[2];
    const float* be1 = (const float*)d_in[3];
    const float* Wmu = (const float*)d_in[4];
    const float* bmu = (const float*)d_in[5];
    const float* Wls = (const float*)d_in[6];
    const float* bls = (const float*)d_in[7];
    const float* Wd1 = (const float*)d_in[8];
    const float* bd1 = (const float*)d_in[9];
    const float* Wd2 = (const float*)d_in[10];
    const float* bd2 = (const float*)d_in[11];
    float* out = (float*)d_out;

    __nv_bfloat16 *xb, *hb, *hdb, *We1t, *Wmlt, *Wd1t, *Wd2t;
    float *kl, *lp, *bml;
    cudaGetSymbolAddress((void**)&xb,   g_xb);
    cudaGetSymbolAddress((void**)&hb,   g_hb);
    cudaGetSymbolAddress((void**)&hdb,  g_hdb);
    cudaGetSymbolAddress((void**)&kl,   g_kl);
    cudaGetSymbolAddress((void**)&lp,   g_lp);
    cudaGetSymbolAddress((void**)&We1t, g_We1t);
    cudaGetSymbolAddress((void**)&Wmlt, g_Wmlt);
    cudaGetSymbolAddress((void**)&Wd1t, g_Wd1t);
    cudaGetSymbolAddress((void**)&Wd2t, g_Wd2t);
    cudaGetSymbolAddress((void**)&bml,  g_bml);

    constexpr int SM_SMALL = GemmCfg<128,128>::SMEM;   // 3 x 32KB + pad
    constexpr int SM_BIG   = GemmCfg<128,256>::SMEM;   // 3 x 48KB + pad

    cudaFuncSetAttribute((const void*)mma_gemm<0,128,128,128,2>, cudaFuncAttributeMaxDynamicSharedMemorySize, SM_SMALL);
    cudaFuncSetAttribute((const void*)mma_gemm<2,128,128,128,2>, cudaFuncAttributeMaxDynamicSharedMemorySize, SM_SMALL);
    cudaFuncSetAttribute((const void*)mma_gemm<3,128,256,256,1>, cudaFuncAttributeMaxDynamicSharedMemorySize, SM_BIG);

    // 0) fused prep
    prep_kernel<<<18817, 256>>>(x, We1, Wmu, Wls, Wd1, Wd2, bmu, bls,
                                xb, We1t, Wmlt, Wd1t, Wd2t, bml);
    // 1) h = relu(x @ We1 + be1) -> bf16
    mma_gemm<0,128,128,128,2><<<dim3(8, 256), 128, SM_SMALL>>>(
        xb, D_IN, We1t, be1, hb, D_H, nullptr, nullptr, nullptr,
        nullptr, nullptr, nullptr, D_IN);
    // 2) [mu|ls] GEMM + fused reparam/KL + hd = relu(z @ Wd1 + bd1) -> hdb
    mma_gemm<3,128,256,256,1><<<dim3(1, 256), 256, SM_BIG>>>(
        hb, D_H, Wmlt, bml, nullptr, 0, nullptr, kl, eps,
        Wd1t, bd1, hdb, D_H);
    // 3) Bernoulli log-lik partials from hd @ Wd2 + bd2
    mma_gemm<2,128,128,128,2><<<dim3(8, 256), 128, SM_SMALL>>>(
        hdb, D_H, Wd2t, bd2, nullptr, 0, xb, lp, nullptr,
        nullptr, nullptr, nullptr, D_H);
    // 4) out = log_px - kl
    finalize_kernel<<<BATCH / 256, 256>>>(kl, lp, out);
}

// round 15
// speedup vs baseline: 1.3637x; 1.0101x over previous
#include <cuda_runtime.h>
#include <cuda_bf16.h>
#include <cstdint>
#include <math.h>

#define BATCH 32768
#define D_IN  1024
#define D_H   1024
#define D_L   128

// ---------------- scratch (__device__ globals; alloc-free rule) -------------
__device__ __align__(16) __nv_bfloat16 g_xb [BATCH * D_IN];
__device__ __align__(16) uint64_t      g_xbit[BATCH * 16];      // 1 bit/elem, 16 u64/row
__device__ __align__(16) __nv_bfloat16 g_hb [BATCH * D_H];
__device__ __align__(16) __nv_bfloat16 g_hdb[BATCH * D_H];
__device__ __align__(16) float         g_kl [BATCH];
__device__ __align__(16) float         g_lp [BATCH * 16];
__device__ __align__(16) __nv_bfloat16 g_We1t[D_H * D_IN];     // [N][K] K-major
__device__ __align__(16) __nv_bfloat16 g_Wmlt[256 * D_H];
__device__ __align__(16) __nv_bfloat16 g_Wd1t[D_H * D_L];
__device__ __align__(16) __nv_bfloat16 g_Wd2t[D_IN * D_H];
__device__ __align__(16) float         g_bml [256];

// ---------------- helpers ----------------------------------------------------
__device__ __forceinline__ uint32_t smem_u32(const void* p) {
    uint32_t a;
    asm("{ .reg .u64 t; cvta.to.shared.u64 t, %1; cvt.u32.u64 %0, t; }" : "=r"(a) : "l"(p));
    return a;
}

#define CP_ASYNC16(dst, src) \
    asm volatile("cp.async.cg.shared.global [%0], [%1], 16;" :: "r"(dst), "l"(src))
#define CP_COMMIT() asm volatile("cp.async.commit_group;" ::: "memory")
#define CP_WAIT0()  asm volatile("cp.async.wait_group 0;" ::: "memory")
#define CP_WAIT1()  asm volatile("cp.async.wait_group 1;" ::: "memory")

__device__ __forceinline__ void ldsm4(uint32_t& r0, uint32_t& r1, uint32_t& r2, uint32_t& r3,
                                      uint32_t addr) {
    asm volatile("ldmatrix.sync.aligned.m8n8.x4.shared.b16 {%0,%1,%2,%3}, [%4];"
                 : "=r"(r0), "=r"(r1), "=r"(r2), "=r"(r3) : "r"(addr));
}

__device__ __forceinline__ void mma16816(float* c, const uint32_t* a, const uint32_t* b) {
    asm volatile("mma.sync.aligned.m16n8k16.row.col.f32.bf16.bf16.f32 "
                 "{%0,%1,%2,%3}, {%4,%5,%6,%7}, {%8,%9}, {%0,%1,%2,%3};"
                 : "+f"(c[0]), "+f"(c[1]), "+f"(c[2]), "+f"(c[3])
                 : "r"(a[0]), "r"(a[1]), "r"(a[2]), "r"(a[3]), "r"(b[0]), "r"(b[1]));
}

// ---------------- HMMA GEMM: C[M,N] = A[M,K] @ Bt[N,K]^T (+epilogue) ---------
// Warp tile 64x64. EPI 0/2: BM=BN=128, NTHR=128 (4 warps), MINB=2 (2 CTA/SM).
// EPI 3: BM=128, BN=256, NTHR=256 (8 warps), MINB=1,
//        fused reparam + KL + hd = relu(z @ W2^T + B2) -> C2.
// 3-stage cp.async pipeline, ONE __syncthreads per K-chunk of 64.
static constexpr int NSTAGE = 3;

template<int BM, int BN> struct GemmCfg {
    static constexpr int STAGE = (BM + BN) * 64 * 2;
    static constexpr int SMEM  = NSTAGE * STAGE + 128;
};

template<int EPI, int BM, int BN, int NTHR, int MINB>
__global__ __launch_bounds__(NTHR, MINB)
void mma_gemm(const __nv_bfloat16* __restrict__ A, int lda,
              const __nv_bfloat16* __restrict__ Bt,
              const float* __restrict__ bias,
              void* __restrict__ Cv, int ldc,
              const uint64_t* __restrict__ XBITS,
              float* __restrict__ LP,
              const float* __restrict__ EPS,
              const __nv_bfloat16* __restrict__ W2,
              const float* __restrict__ B2,
              __nv_bfloat16* __restrict__ C2, int K)
{
    extern __shared__ char smraw[];
    uint32_t raw = smem_u32(smraw);
    uint32_t sbase = (raw + 127u) & ~127u;
    char* sm = smraw + (sbase - raw);

    constexpr int NWARP = NTHR / 32;
    constexpr int WM  = 2;
    constexpr int WNG = NWARP / WM;
    constexpr int WTN = BN / WNG;              // 64
    constexpr int NT  = WTN / 8;               // 8
    constexpr int A_BYTES = BM * 64 * 2;
    constexpr int STAGE_BYTES = GemmCfg<BM, BN>::STAGE;
    constexpr int AI = BM * 8 / NTHR, BI = BN * 8 / NTHR;

    const int tid  = threadIdx.x, lane = tid & 31, wid = tid >> 5;
    const int wm   = wid % WM, wn = wid / WM;
    const int bn   = blockIdx.x;
    const int m0   = blockIdx.y * BM, col0 = bn * BN;

    const __nv_bfloat16* Ag = A  + (size_t)m0   * lda;
    const __nv_bfloat16* Bg = Bt + (size_t)col0 * K;

    const int T = K >> 6;
    const int P = (T < NSTAGE - 1) ? T : (NSTAGE - 1);

    float acc[4][NT][4];
#pragma unroll
    for (int mt = 0; mt < 4; ++mt)
#pragma unroll
        for (int nt = 0; nt < NT; ++nt)
#pragma unroll
            for (int q = 0; q < 4; ++q) acc[mt][nt][q] = 0.f;

    auto issue_stage = [&](int kt) {
        uint32_t sA = sbase + (uint32_t)(kt % NSTAGE) * STAGE_BYTES;
        uint32_t sB = sA + A_BYTES;
        const __nv_bfloat16* Ak = Ag + kt * 64;
        const __nv_bfloat16* Bk = Bg + kt * 64;
#pragma unroll
        for (int i = 0; i < AI; ++i) {
            int idx = tid + i * NTHR;
            int rr = idx >> 3, cc = idx & 7;
            uint32_t sw = (uint32_t)(rr * 128 + ((cc ^ (rr & 7)) << 4));
            CP_ASYNC16(sA + sw, Ak + (size_t)rr * lda + cc * 8);
        }
#pragma unroll
        for (int i = 0; i < BI; ++i) {
            int idx = tid + i * NTHR;
            int rr = idx >> 3, cc = idx & 7;
            uint32_t sw = (uint32_t)(rr * 128 + ((cc ^ (rr & 7)) << 4));
            CP_ASYNC16(sB + sw, Bk + (size_t)rr * K + cc * 8);
        }
        CP_COMMIT();
    };

    for (int kt = 0; kt < P; ++kt) issue_stage(kt);
    int committed = P;

    const int g = lane >> 3, lq = lane & 7;

    // row&7 == lq for all ldsm rows -> per-kk swizzle offsets shared by all loads
    uint32_t aRow[4], bRow[4];
#pragma unroll
    for (int mt = 0; mt < 4; ++mt)
        aRow[mt] = (uint32_t)((wm * 64 + mt * 16 + (g & 1) * 8 + lq) * 128);
#pragma unroll
    for (int p = 0; p < 4; ++p)
        bRow[p] = (uint32_t)((wn * WTN + (p * 2 + (g >> 1)) * 8 + lq) * 128);

    for (int t = 0; t < T; ++t) {
        int allow = committed - t - 1;
        if (allow >= 1) { CP_WAIT1(); } else { CP_WAIT0(); }
        __syncthreads();

        if (t + NSTAGE - 1 < T) { issue_stage(t + NSTAGE - 1); committed++; }

        uint32_t sA = sbase + (uint32_t)(t % NSTAGE) * STAGE_BYTES;
        uint32_t sB = sA + A_BYTES;

#pragma unroll
        for (int kk = 0; kk < 4; ++kk) {
            const uint32_t aOff = (uint32_t)(((kk * 2 + (g >> 1)) ^ lq) << 4);
            const uint32_t bOff = (uint32_t)(((kk * 2 + (g & 1)) ^ lq) << 4);
            uint32_t a[4][4];
#pragma unroll
            for (int mt = 0; mt < 4; ++mt)
                ldsm4(a[mt][0], a[mt][1], a[mt][2], a[mt][3], sA + aRow[mt] + aOff);
            uint32_t b[NT][2];
#pragma unroll
            for (int p = 0; p < 4; ++p) {
                uint32_t r0, r1, r2, r3;
                ldsm4(r0, r1, r2, r3, sB + bRow[p] + bOff);
                b[p * 2][0] = r0; b[p * 2][1] = r1;
                b[p * 2 + 1][0] = r2; b[p * 2 + 1][1] = r3;
            }
#pragma unroll
            for (int mt = 0; mt < 4; ++mt)
#pragma unroll
                for (int nt = 0; nt < NT; ++nt)
                    mma16816(acc[mt][nt], a[mt], b[nt]);
        }
    }

    // ---------------- epilogue ----------------
    const int rbase = m0 + wm * 64 + (lane >> 2);
    const int cq    = (lane & 3) * 2;

    float bv[2 * NT];
#pragma unroll
    for (int nt = 0; nt < NT; ++nt) {
        int col = (EPI == 3 ? 0 : col0) + wn * WTN + nt * 8 + cq;
        bv[2 * nt]     = __ldg(bias + col);
        bv[2 * nt + 1] = __ldg(bias + col + 1);
    }

    if (EPI == 0) {
        __nv_bfloat16* C = (__nv_bfloat16*)Cv;
#pragma unroll
        for (int mt = 0; mt < 4; ++mt) {
            int r0 = rbase + mt * 16;
#pragma unroll
            for (int nt = 0; nt < NT; ++nt) {
                int col = col0 + wn * WTN + nt * 8 + cq;
                float v0 = fmaxf(acc[mt][nt][0] + bv[2*nt],   0.f);
                float v1 = fmaxf(acc[mt][nt][1] + bv[2*nt+1], 0.f);
                float v2 = fmaxf(acc[mt][nt][2] + bv[2*nt],   0.f);
                float v3 = fmaxf(acc[mt][nt][3] + bv[2*nt+1], 0.f);
                __nv_bfloat162 p0 = __float22bfloat162_rn(make_float2(v0, v1));
                __nv_bfloat162 p1 = __float22bfloat162_rn(make_float2(v2, v3));
                *(uint32_t*)(C + (size_t)r0 * ldc + col)       = *(uint32_t*)&p0;
                *(uint32_t*)(C + (size_t)(r0 + 8) * ldc + col) = *(uint32_t*)&p1;
            }
        }
    } else if (EPI == 2) {
        // Bernoulli log-lik with bit-packed x (16 u64 per row); grouped 4-wide log.
        const int wIdx = (col0 + wn * WTN) >> 6;     // u64 word index within row
#pragma unroll
        for (int mt = 0; mt < 4; ++mt) {
            int r0 = rbase + mt * 16;
            uint64_t w0 = __ldg(XBITS + (size_t)r0 * 16 + wIdx);
            uint64_t w1 = __ldg(XBITS + (size_t)(r0 + 8) * 16 + wIdx);
            float s0 = 0.f, s1 = 0.f;
#pragma unroll
            for (int nt = 0; nt < NT; nt += 2) {
                float t[8];
#pragma unroll
                for (int j = 0; j < 2; ++j) {
                    int ntj = nt + j;
                    int bi = ntj * 8 + cq;
                    float a0 = acc[mt][ntj][0] + bv[2*ntj];
                    float a1 = acc[mt][ntj][1] + bv[2*ntj+1];
                    float a2 = acc[mt][ntj][2] + bv[2*ntj];
                    float a3 = acc[mt][ntj][3] + bv[2*ntj+1];
                    t[j*4+0] = ((w0 >> bi) & 1ull)       ? -a0 : a0;
                    t[j*4+1] = ((w0 >> (bi + 1)) & 1ull) ? -a1 : a1;
                    t[j*4+2] = ((w1 >> bi) & 1ull)       ? -a2 : a2;
                    t[j*4+3] = ((w1 >> (bi + 1)) & 1ull) ? -a3 : a3;
                }
                float p0 = (1.f + __expf(-fabsf(t[0]))) * (1.f + __expf(-fabsf(t[1])));
                p0 *= (1.f + __expf(-fabsf(t[4]))) * (1.f + __expf(-fabsf(t[5])));
                float p1 = (1.f + __expf(-fabsf(t[2]))) * (1.f + __expf(-fabsf(t[3])));
                p1 *= (1.f + __expf(-fabsf(t[6]))) * (1.f + __expf(-fabsf(t[7])));
                s0 += fmaxf(t[0], 0.f) + fmaxf(t[1], 0.f) + fmaxf(t[4], 0.f) + fmaxf(t[5], 0.f)
                    + __logf(p0);
                s1 += fmaxf(t[2], 0.f) + fmaxf(t[3], 0.f) + fmaxf(t[6], 0.f) + fmaxf(t[7], 0.f)
                    + __logf(p1);
            }
            s0 += __shfl_xor_sync(0xffffffffu, s0, 1);
            s0 += __shfl_xor_sync(0xffffffffu, s0, 2);
            s1 += __shfl_xor_sync(0xffffffffu, s1, 1);
            s1 += __shfl_xor_sync(0xffffffffu, s1, 2);
            if ((lane & 3) == 0) {
                LP[(size_t)r0 * 16 + bn * 2 + wn]       = -s0;
                LP[(size_t)(r0 + 8) * 16 + bn * 2 + wn] = -s1;
            }
        }
    } else {
        // EPI 3: fused reparam + KL + hd GEMM. BM=128, BN=256 (mu|ls), NTHR=256.
        constexpr int SPAD = 258;
        float* S = (float*)sm;
        __syncthreads();
        const int rl = wm * 64 + (lane >> 2);
#pragma unroll
        for (int mt = 0; mt < 4; ++mt) {
            int r0 = rl + mt * 16;
#pragma unroll
            for (int nt = 0; nt < NT; ++nt) {
                int col = wn * WTN + nt * 8 + cq;
                *(float2*)&S[(size_t)r0 * SPAD + col] =
                    make_float2(acc[mt][nt][0] + bv[2*nt], acc[mt][nt][1] + bv[2*nt+1]);
                *(float2*)&S[(size_t)(r0 + 8) * SPAD + col] =
                    make_float2(acc[mt][nt][2] + bv[2*nt], acc[mt][nt][3] + bv[2*nt+1]);
            }
        }
        __syncthreads();

        const int r = tid >> 1, h = tid & 1;
        const size_t grow = (size_t)m0 + r;
        const float* erow = EPS + grow * 128 + h * 64;
        float kla = 0.f;
        uint32_t zbuf[32];
#pragma unroll
        for (int j = 0; j < 32; ++j) {
            int c = h * 64 + 2 * j;
            float mu0 = S[(size_t)r * SPAD + c];
            float mu1 = S[(size_t)r * SPAD + c + 1];
            float l0  = S[(size_t)r * SPAD + c + 128];
            float l1  = S[(size_t)r * SPAD + c + 129];
            float2 ep = *(const float2*)&erow[2 * j];
            float s0 = __expf(l0), s1 = __expf(l1);
            float z0 = fmaf(s0, ep.x, mu0), z1 = fmaf(s1, ep.y, mu1);
            __nv_bfloat162 p = __float22bfloat162_rn(make_float2(z0, z1));
            zbuf[j] = *(uint32_t*)&p;
            kla += s0 * s0 + mu0 * mu0 - 2.f * l0 - 1.f;
            kla += s1 * s1 + mu1 * mu1 - 2.f * l1 - 1.f;
        }
        kla += __shfl_xor_sync(0xffffffffu, kla, 1);
        if (h == 0) LP[grow] = 0.5f * kla;
        __syncthreads();

        // stage z into smem as two swizzled A-chunks (16KB each, at sbase)
#pragma unroll
        for (int cc = 0; cc < 8; ++cc) {
            uint32_t off = (uint32_t)h * 16384u +
                           (uint32_t)(r * 128 + ((cc ^ (r & 7)) << 4));
            *(int4*)(sm + off) = ((int4*)zbuf)[cc];
        }

        auto issue_b = [&](int nb) {
            uint32_t sB = sbase + 32768u + (uint32_t)(nb % 3) * 32768u;
            const __nv_bfloat16* Bk = W2 + (size_t)(nb * 128) * 128;
#pragma unroll
            for (int i = 0; i < 2048 / NTHR; ++i) {
                int idx = tid + i * NTHR;
                int tt = idx >> 10;
                int rr = (idx >> 3) & 127;
                int cc = idx & 7;
                uint32_t sw = (uint32_t)(rr * 128 + ((cc ^ (rr & 7)) << 4));
                CP_ASYNC16(sB + (uint32_t)tt * 16384u + sw,
                           Bk + (size_t)rr * 128 + tt * 64 + cc * 8);
            }
            CP_COMMIT();
        };
        issue_b(0); issue_b(1);

        for (int nb = 0; nb < 8; ++nb) {
            if (nb < 7) { CP_WAIT1(); } else { CP_WAIT0(); }
            __syncthreads();
            if (nb + 2 < 8) issue_b(nb + 2);

            uint32_t sB = sbase + 32768u + (uint32_t)(nb % 3) * 32768u;
            float acc2[4][4][4];
#pragma unroll
            for (int mt = 0; mt < 4; ++mt)
#pragma unroll
                for (int nt = 0; nt < 4; ++nt)
#pragma unroll
                    for (int q = 0; q < 4; ++q) acc2[mt][nt][q] = 0.f;

#pragma unroll
            for (int t = 0; t < 2; ++t) {
#pragma unroll
                for (int kk = 0; kk < 4; ++kk) {
                    uint32_t a[4][4];
#pragma unroll
                    for (int mt = 0; mt < 4; ++mt) {
                        int row = wm * 64 + mt * 16 + (g & 1) * 8 + lq;
                        int kc  = kk * 2 + (g >> 1);
                        uint32_t ad = sbase + (uint32_t)t * 16384u +
                                      (uint32_t)(row * 128 + ((kc ^ (row & 7)) << 4));
                        ldsm4(a[mt][0], a[mt][1], a[mt][2], a[mt][3], ad);
                    }
                    uint32_t b[4][2];
#pragma unroll
                    for (int p = 0; p < 2; ++p) {
                        int row = wn * 32 + (p * 2 + (g >> 1)) * 8 + lq;
                        int kc  = kk * 2 + (g & 1);
                        uint32_t ad = sB + (uint32_t)t * 16384u +
                                      (uint32_t)(row * 128 + ((kc ^ (row & 7)) << 4));
                        uint32_t r0, r1, r2, r3;
                        ldsm4(r0, r1, r2, r3, ad);
                        b[p * 2][0] = r0; b[p * 2][1] = r1;
                        b[p * 2 + 1][0] = r2; b[p * 2 + 1][1] = r3;
                    }
#pragma unroll
                    for (int mt = 0; mt < 4; ++mt)
#pragma unroll
                        for (int nt = 0; nt < 4; ++nt)
                            mma16816(acc2[mt][nt], a[mt], b[nt]);
                }
            }
#pragma unroll
            for (int mt = 0; mt < 4; ++mt) {
                int r0 = rbase + mt * 16;
#pragma unroll
                for (int nt = 0; nt < 4; ++nt) {
                    int col = nb * 128 + wn * 32 + nt * 8 + cq;
                    float b0 = __ldg(B2 + col), b1 = __ldg(B2 + col + 1);
                    float v0 = fmaxf(acc2[mt][nt][0] + b0, 0.f);
                    float v1 = fmaxf(acc2[mt][nt][1] + b1, 0.f);
                    float v2 = fmaxf(acc2[mt][nt][2] + b0, 0.f);
                    float v3 = fmaxf(acc2[mt][nt][3] + b1, 0.f);
                    __nv_bfloat162 p0 = __float22bfloat162_rn(make_float2(v0, v1));
                    __nv_bfloat162 p1 = __float22bfloat162_rn(make_float2(v2, v3));
                    *(uint32_t*)(C2 + (size_t)r0 * D_H + col)       = *(uint32_t*)&p0;
                    *(uint32_t*)(C2 + (size_t)(r0 + 8) * D_H + col) = *(uint32_t*)&p1;
                }
            }
        }
    }
}

// ---------------- fused prep kernel ------------------------------------------
__device__ __forceinline__ void do_transpose(float (*ts)[33],
                                             const float* __restrict__ in,
                                             __nv_bfloat16* __restrict__ out,
                                             int K, int N, int rowOff, int bx, int by, int tid) {
    int tx = tid & 31, ty = tid >> 5;
    int k0 = by * 32, n0 = bx * 32;
    for (int j = ty; j < 32; j += 8)
        ts[j][tx] = in[(size_t)(k0 + j) * N + n0 + tx];
    __syncthreads();
    for (int j = ty; j < 32; j += 8)
        out[(size_t)(rowOff + n0 + j) * K + k0 + tx] = __float2bfloat16(ts[tx][j]);
}

__global__ __launch_bounds__(256)
void prep_kernel(const float* __restrict__ x,
                 const float* __restrict__ We1, const float* __restrict__ Wmu,
                 const float* __restrict__ Wls, const float* __restrict__ Wd1,
                 const float* __restrict__ Wd2, const float* __restrict__ bmu,
                 const float* __restrict__ bls,
                 __nv_bfloat16* __restrict__ xb, uint8_t* __restrict__ xbit,
                 __nv_bfloat16* __restrict__ We1t,
                 __nv_bfloat16* __restrict__ Wmlt, __nv_bfloat16* __restrict__ Wd1t,
                 __nv_bfloat16* __restrict__ Wd2t, float* __restrict__ bml)
{
    __shared__ float ts[32][33];
    const int b = blockIdx.x, tid = threadIdx.x;
    if (b < 16384) {
        size_t i = ((size_t)b * 256 + tid) * 8;
        float4 a = *(const float4*)(x + i);
        float4 c = *(const float4*)(x + i + 4);
        __nv_bfloat162 p[4];
        p[0] = __float22bfloat162_rn(make_float2(a.x, a.y));
        p[1] = __float22bfloat162_rn(make_float2(a.z, a.w));
        p[2] = __float22bfloat162_rn(make_float2(c.x, c.y));
        p[3] = __float22bfloat162_rn(make_float2(c.z, c.w));
        *(int4*)(xb + i) = *(int4*)p;
        // bit-pack: byte index = global elem index / 8 = b*256 + tid
        uint32_t bits = (a.x > 0.5f ? 1u : 0u)  | (a.y > 0.5f ? 2u : 0u)
                      | (a.z > 0.5f ? 4u : 0u)  | (a.w > 0.5f ? 8u : 0u)
                      | (c.x > 0.5f ? 16u : 0u) | (c.y > 0.5f ? 32u : 0u)
                      | (c.z > 0.5f ? 64u : 0u) | (c.w > 0.5f ? 128u : 0u);
        xbit[(size_t)b * 256 + tid] = (uint8_t)bits;
    } else if (b < 17408) {
        int r = b - 16384;  do_transpose(ts, We1, We1t, 1024, 1024, 0,   r % 32, r / 32, tid);
    } else if (b < 17536) {
        int r = b - 17408;  do_transpose(ts, Wmu, Wmlt, 1024, 128,  0,   r % 4,  r / 4,  tid);
    } else if (b < 17664) {
        int r = b - 17536;  do_transpose(ts, Wls, Wmlt, 1024, 128,  128, r % 4,  r / 4,  tid);
    } else if (b < 17792) {
        int r = b - 17664;  do_transpose(ts, Wd1, Wd1t, 128,  1024, 0,   r % 32, r / 32, tid);
    } else if (b < 18816) {
        int r = b - 17792;  do_transpose(ts, Wd2, Wd2t, 1024, 1024, 0,   r % 32, r / 32, tid);
    } else {
        bml[tid] = (tid < 128) ? bmu[tid] : bls[tid - 128];
    }
}

__global__ void finalize_kernel(const float* __restrict__ kl_, const float* __restrict__ lp_,
                                float* __restrict__ out) {
    int r = blockIdx.x * blockDim.x + threadIdx.x;
    float s = 0.f;
#pragma unroll
    for (int j = 0; j < 16; j++) s += lp_[(size_t)r * 16 + j];
    out[r] = s - kl_[r];
}

// ---------------- launch ------------------------------------------------------
extern "C" void kernel_launch(void* const* d_in, const int* in_sizes, int n_in,
                              void* d_out, int out_size)
{
    const float* x   = (const float*)d_in[0];
    const float* eps = (const float*)d_in[1];
    const float* We1 = (const float*)d_in[2];
    const float* be1 = (const float*)d_in[3];
    const float* Wmu = (const float*)d_in[4];
    const float* bmu = (const float*)d_in[5];
    const float* Wls = (const float*)d_in[6];
    const float* bls = (const float*)d_in[7];
    const float* Wd1 = (const float*)d_in[8];
    const float* bd1 = (const float*)d_in[9];
    const float* Wd2 = (const float*)d_in[10];
    const float* bd2 = (const float*)d_in[11];
    float* out = (float*)d_out;

    __nv_bfloat16 *xb, *hb, *hdb, *We1t, *Wmlt, *Wd1t, *Wd2t;
    uint64_t* xbit;
    float *kl, *lp, *bml;
    cudaGetSymbolAddress((void**)&xb,   g_xb);
    cudaGetSymbolAddress((void**)&xbit, g_xbit);
    cudaGetSymbolAddress((void**)&hb,   g_hb);
    cudaGetSymbolAddress((void**)&hdb,  g_hdb);
    cudaGetSymbolAddress((void**)&kl,   g_kl);
    cudaGetSymbolAddress((void**)&lp,   g_lp);
    cudaGetSymbolAddress((void**)&We1t, g_We1t);
    cudaGetSymbolAddress((void**)&Wmlt, g_Wmlt);
    cudaGetSymbolAddress((void**)&Wd1t, g_Wd1t);
    cudaGetSymbolAddress((void**)&Wd2t, g_Wd2t);
    cudaGetSymbolAddress((void**)&bml,  g_bml);

    constexpr int SM_SMALL = GemmCfg<128,128>::SMEM;   // 3 x 32KB + pad
    constexpr int SM_BIG   = GemmCfg<128,256>::SMEM;   // 3 x 48KB + pad

    cudaFuncSetAttribute((const void*)mma_gemm<0,128,128,128,2>, cudaFuncAttributeMaxDynamicSharedMemorySize, SM_SMALL);
    cudaFuncSetAttribute((const void*)mma_gemm<2,128,128,128,2>, cudaFuncAttributeMaxDynamicSharedMemorySize, SM_SMALL);
    cudaFuncSetAttribute((const void*)mma_gemm<3,128,256,256,1>, cudaFuncAttributeMaxDynamicSharedMemorySize, SM_BIG);

    // 0) fused prep (also bit-packs x)
    prep_kernel<<<18817, 256>>>(x, We1, Wmu, Wls, Wd1, Wd2, bmu, bls,
                                xb, (uint8_t*)xbit, We1t, Wmlt, Wd1t, Wd2t, bml);
    // 1) h = relu(x @ We1 + be1) -> bf16
    mma_gemm<0,128,128,128,2><<<dim3(8, 256), 128, SM_SMALL>>>(
        xb, D_IN, We1t, be1, hb, D_H, nullptr, nullptr, nullptr,
        nullptr, nullptr, nullptr, D_IN);
    // 2) [mu|ls] GEMM + fused reparam/KL + hd = relu(z @ Wd1 + bd1) -> hdb
    mma_gemm<3,128,256,256,1><<<dim3(1, 256), 256, SM_BIG>>>(
        hb, D_H, Wmlt, bml, nullptr, 0, nullptr, kl, eps,
        Wd1t, bd1, hdb, D_H);
    // 3) Bernoulli log-lik partials from hd @ Wd2 + bd2 (bit-packed x)
    mma_gemm<2,128,128,128,2><<<dim3(8, 256), 128, SM_SMALL>>>(
        hdb, D_H, Wd2t, bd2, nullptr, 0, xbit, lp, nullptr,
        nullptr, nullptr, nullptr, D_H);
    // 4) out = log_px - kl
    finalize_kernel<<<BATCH / 256, 256>>>(kl, lp, out);
}

// round 16
// speedup vs baseline: 1.3683x; 1.0034x over previous
#include <cuda_runtime.h>
#include <cuda_bf16.h>
#include <cstdint>
#include <math.h>

#define BATCH 32768
#define D_IN  1024
#define D_H   1024
#define D_L   128

// ---------------- scratch (__device__ globals; alloc-free rule) -------------
__device__ __align__(16) __nv_bfloat16 g_xb [BATCH * D_IN];
__device__ __align__(16) uint64_t      g_xbit[BATCH * 16];      // 1 bit/elem, 16 u64/row
__device__ __align__(16) __nv_bfloat16 g_hb [BATCH * D_H];
__device__ __align__(16) __nv_bfloat16 g_hdb[BATCH * D_H];
__device__ __align__(16) float         g_kl [BATCH];
__device__ __align__(16) float         g_lp [BATCH * 16];
__device__ __align__(16) __nv_bfloat16 g_We1t[D_H * D_IN];     // [N][K] K-major
__device__ __align__(16) __nv_bfloat16 g_Wmlt[256 * D_H];
__device__ __align__(16) __nv_bfloat16 g_Wd1t[D_H * D_L];
__device__ __align__(16) __nv_bfloat16 g_Wd2t[D_IN * D_H];
__device__ __align__(16) float         g_bml [256];

// ---------------- helpers ----------------------------------------------------
__device__ __forceinline__ uint32_t smem_u32(const void* p) {
    uint32_t a;
    asm("{ .reg .u64 t; cvta.to.shared.u64 t, %1; cvt.u32.u64 %0, t; }" : "=r"(a) : "l"(p));
    return a;
}

#define CP_ASYNC16(dst, src) \
    asm volatile("cp.async.cg.shared.global [%0], [%1], 16;" :: "r"(dst), "l"(src))
#define CP_COMMIT() asm volatile("cp.async.commit_group;" ::: "memory")
#define CP_WAIT0()  asm volatile("cp.async.wait_group 0;" ::: "memory")
#define CP_WAIT1()  asm volatile("cp.async.wait_group 1;" ::: "memory")
#define CP_WAIT2()  asm volatile("cp.async.wait_group 2;" ::: "memory")

__device__ __forceinline__ void ldsm4(uint32_t& r0, uint32_t& r1, uint32_t& r2, uint32_t& r3,
                                      uint32_t addr) {
    asm volatile("ldmatrix.sync.aligned.m8n8.x4.shared.b16 {%0,%1,%2,%3}, [%4];"
                 : "=r"(r0), "=r"(r1), "=r"(r2), "=r"(r3) : "r"(addr));
}

__device__ __forceinline__ void mma16816(float* c, const uint32_t* a, const uint32_t* b) {
    asm volatile("mma.sync.aligned.m16n8k16.row.col.f32.bf16.bf16.f32 "
                 "{%0,%1,%2,%3}, {%4,%5,%6,%7}, {%8,%9}, {%0,%1,%2,%3};"
                 : "+f"(c[0]), "+f"(c[1]), "+f"(c[2]), "+f"(c[3])
                 : "r"(a[0]), "r"(a[1]), "r"(a[2]), "r"(a[3]), "r"(b[0]), "r"(b[1]));
}

// ---------------- HMMA GEMM: C[M,N] = A[M,K] @ Bt[N,K]^T (+epilogue) ---------
// Warp tile 64x64. EPI 0/2: BM=BN=128, NTHR=128, NST=3, MINB=2 (2 CTA/SM).
// EPI 3: BM=128, BN=256, NTHR=256, NST=4 (deeper pipeline: 1 CTA/SM, single
//        barrier domain), MINB=1; fused reparam + KL + hd GEMM -> C2.
template<int BM, int BN, int NST> struct GemmCfg {
    static constexpr int STAGE = (BM + BN) * 64 * 2;
    static constexpr int SMEM  = NST * STAGE + 128;
};

template<int EPI, int BM, int BN, int NTHR, int NST, int MINB>
__global__ __launch_bounds__(NTHR, MINB)
void mma_gemm(const __nv_bfloat16* __restrict__ A, int lda,
              const __nv_bfloat16* __restrict__ Bt,
              const float* __restrict__ bias,
              void* __restrict__ Cv, int ldc,
              const uint64_t* __restrict__ XBITS,
              float* __restrict__ LP,
              const float* __restrict__ EPS,
              const __nv_bfloat16* __restrict__ W2,
              const float* __restrict__ B2,
              __nv_bfloat16* __restrict__ C2, int K)
{
    extern __shared__ char smraw[];
    uint32_t raw = smem_u32(smraw);
    uint32_t sbase = (raw + 127u) & ~127u;
    char* sm = smraw + (sbase - raw);

    constexpr int NWARP = NTHR / 32;
    constexpr int WM  = 2;
    constexpr int WNG = NWARP / WM;
    constexpr int WTN = BN / WNG;              // 64
    constexpr int NT  = WTN / 8;               // 8
    constexpr int A_BYTES = BM * 64 * 2;
    constexpr int STAGE_BYTES = GemmCfg<BM, BN, NST>::STAGE;
    constexpr int AI = BM * 8 / NTHR, BI = BN * 8 / NTHR;

    const int tid  = threadIdx.x, lane = tid & 31, wid = tid >> 5;
    const int wm   = wid % WM, wn = wid / WM;
    const int bn   = blockIdx.x;
    const int m0   = blockIdx.y * BM, col0 = bn * BN;

    const __nv_bfloat16* Ag = A  + (size_t)m0   * lda;
    const __nv_bfloat16* Bg = Bt + (size_t)col0 * K;

    const int T = K >> 6;
    const int P = (T < NST - 1) ? T : (NST - 1);

    float acc[4][NT][4];
#pragma unroll
    for (int mt = 0; mt < 4; ++mt)
#pragma unroll
        for (int nt = 0; nt < NT; ++nt)
#pragma unroll
            for (int q = 0; q < 4; ++q) acc[mt][nt][q] = 0.f;

    auto issue_stage = [&](int kt) {
        uint32_t sA = sbase + (uint32_t)(kt % NST) * STAGE_BYTES;
        uint32_t sB = sA + A_BYTES;
        const __nv_bfloat16* Ak = Ag + kt * 64;
        const __nv_bfloat16* Bk = Bg + kt * 64;
#pragma unroll
        for (int i = 0; i < AI; ++i) {
            int idx = tid + i * NTHR;
            int rr = idx >> 3, cc = idx & 7;
            uint32_t sw = (uint32_t)(rr * 128 + ((cc ^ (rr & 7)) << 4));
            CP_ASYNC16(sA + sw, Ak + (size_t)rr * lda + cc * 8);
        }
#pragma unroll
        for (int i = 0; i < BI; ++i) {
            int idx = tid + i * NTHR;
            int rr = idx >> 3, cc = idx & 7;
            uint32_t sw = (uint32_t)(rr * 128 + ((cc ^ (rr & 7)) << 4));
            CP_ASYNC16(sB + sw, Bk + (size_t)rr * K + cc * 8);
        }
        CP_COMMIT();
    };

    for (int kt = 0; kt < P; ++kt) issue_stage(kt);
    int committed = P;

    const int g = lane >> 3, lq = lane & 7;

    uint32_t aRow[4], bRow[4];
#pragma unroll
    for (int mt = 0; mt < 4; ++mt)
        aRow[mt] = (uint32_t)((wm * 64 + mt * 16 + (g & 1) * 8 + lq) * 128);
#pragma unroll
    for (int p = 0; p < 4; ++p)
        bRow[p] = (uint32_t)((wn * WTN + (p * 2 + (g >> 1)) * 8 + lq) * 128);

    for (int t = 0; t < T; ++t) {
        int allow = committed - t - 1;
        if (NST >= 4 && allow >= 2) { CP_WAIT2(); }
        else if (allow >= 1)        { CP_WAIT1(); }
        else                        { CP_WAIT0(); }
        __syncthreads();

        if (t + NST - 1 < T) { issue_stage(t + NST - 1); committed++; }

        uint32_t sA = sbase + (uint32_t)(t % NST) * STAGE_BYTES;
        uint32_t sB = sA + A_BYTES;

#pragma unroll
        for (int kk = 0; kk < 4; ++kk) {
            const uint32_t aOff = (uint32_t)(((kk * 2 + (g >> 1)) ^ lq) << 4);
            const uint32_t bOff = (uint32_t)(((kk * 2 + (g & 1)) ^ lq) << 4);
            uint32_t a[4][4];
#pragma unroll
            for (int mt = 0; mt < 4; ++mt)
                ldsm4(a[mt][0], a[mt][1], a[mt][2], a[mt][3], sA + aRow[mt] + aOff);
            uint32_t b[NT][2];
#pragma unroll
            for (int p = 0; p < 4; ++p) {
                uint32_t r0, r1, r2, r3;
                ldsm4(r0, r1, r2, r3, sB + bRow[p] + bOff);
                b[p * 2][0] = r0; b[p * 2][1] = r1;
                b[p * 2 + 1][0] = r2; b[p * 2 + 1][1] = r3;
            }
#pragma unroll
            for (int mt = 0; mt < 4; ++mt)
#pragma unroll
                for (int nt = 0; nt < NT; ++nt)
                    mma16816(acc[mt][nt], a[mt], b[nt]);
        }
    }

    // ---------------- epilogue ----------------
    const int rbase = m0 + wm * 64 + (lane >> 2);
    const int cq    = (lane & 3) * 2;

    float bv[2 * NT];
#pragma unroll
    for (int nt = 0; nt < NT; ++nt) {
        int col = (EPI == 3 ? 0 : col0) + wn * WTN + nt * 8 + cq;
        bv[2 * nt]     = __ldg(bias + col);
        bv[2 * nt + 1] = __ldg(bias + col + 1);
    }

    if (EPI == 0) {
        __nv_bfloat16* C = (__nv_bfloat16*)Cv;
#pragma unroll
        for (int mt = 0; mt < 4; ++mt) {
            int r0 = rbase + mt * 16;
#pragma unroll
            for (int nt = 0; nt < NT; ++nt) {
                int col = col0 + wn * WTN + nt * 8 + cq;
                float v0 = fmaxf(acc[mt][nt][0] + bv[2*nt],   0.f);
                float v1 = fmaxf(acc[mt][nt][1] + bv[2*nt+1], 0.f);
                float v2 = fmaxf(acc[mt][nt][2] + bv[2*nt],   0.f);
                float v3 = fmaxf(acc[mt][nt][3] + bv[2*nt+1], 0.f);
                __nv_bfloat162 p0 = __float22bfloat162_rn(make_float2(v0, v1));
                __nv_bfloat162 p1 = __float22bfloat162_rn(make_float2(v2, v3));
                *(uint32_t*)(C + (size_t)r0 * ldc + col)       = *(uint32_t*)&p0;
                *(uint32_t*)(C + (size_t)(r0 + 8) * ldc + col) = *(uint32_t*)&p1;
            }
        }
    } else if (EPI == 2) {
        // Bernoulli log-lik with bit-packed x (16 u64 per row); grouped 4-wide log.
        const int wIdx = (col0 + wn * WTN) >> 6;
#pragma unroll
        for (int mt = 0; mt < 4; ++mt) {
            int r0 = rbase + mt * 16;
            uint64_t w0 = __ldg(XBITS + (size_t)r0 * 16 + wIdx);
            uint64_t w1 = __ldg(XBITS + (size_t)(r0 + 8) * 16 + wIdx);
            float s0 = 0.f, s1 = 0.f;
#pragma unroll
            for (int nt = 0; nt < NT; nt += 2) {
                float t[8];
#pragma unroll
                for (int j = 0; j < 2; ++j) {
                    int ntj = nt + j;
                    int bi = ntj * 8 + cq;
                    float a0 = acc[mt][ntj][0] + bv[2*ntj];
                    float a1 = acc[mt][ntj][1] + bv[2*ntj+1];
                    float a2 = acc[mt][ntj][2] + bv[2*ntj];
                    float a3 = acc[mt][ntj][3] + bv[2*ntj+1];
                    t[j*4+0] = ((w0 >> bi) & 1ull)       ? -a0 : a0;
                    t[j*4+1] = ((w0 >> (bi + 1)) & 1ull) ? -a1 : a1;
                    t[j*4+2] = ((w1 >> bi) & 1ull)       ? -a2 : a2;
                    t[j*4+3] = ((w1 >> (bi + 1)) & 1ull) ? -a3 : a3;
                }
                float p0 = (1.f + __expf(-fabsf(t[0]))) * (1.f + __expf(-fabsf(t[1])));
                p0 *= (1.f + __expf(-fabsf(t[4]))) * (1.f + __expf(-fabsf(t[5])));
                float p1 = (1.f + __expf(-fabsf(t[2]))) * (1.f + __expf(-fabsf(t[3])));
                p1 *= (1.f + __expf(-fabsf(t[6]))) * (1.f + __expf(-fabsf(t[7])));
                s0 += fmaxf(t[0], 0.f) + fmaxf(t[1], 0.f) + fmaxf(t[4], 0.f) + fmaxf(t[5], 0.f)
                    + __logf(p0);
                s1 += fmaxf(t[2], 0.f) + fmaxf(t[3], 0.f) + fmaxf(t[6], 0.f) + fmaxf(t[7], 0.f)
                    + __logf(p1);
            }
            s0 += __shfl_xor_sync(0xffffffffu, s0, 1);
            s0 += __shfl_xor_sync(0xffffffffu, s0, 2);
            s1 += __shfl_xor_sync(0xffffffffu, s1, 1);
            s1 += __shfl_xor_sync(0xffffffffu, s1, 2);
            if ((lane & 3) == 0) {
                LP[(size_t)r0 * 16 + bn * 2 + wn]       = -s0;
                LP[(size_t)(r0 + 8) * 16 + bn * 2 + wn] = -s1;
            }
        }
    } else {
        // EPI 3: fused reparam + KL + hd GEMM. BM=128, BN=256 (mu|ls), NTHR=256.
        constexpr int SPAD = 258;
        float* S = (float*)sm;
        __syncthreads();
        const int rl = wm * 64 + (lane >> 2);
#pragma unroll
        for (int mt = 0; mt < 4; ++mt) {
            int r0 = rl + mt * 16;
#pragma unroll
            for (int nt = 0; nt < NT; ++nt) {
                int col = wn * WTN + nt * 8 + cq;
                *(float2*)&S[(size_t)r0 * SPAD + col] =
                    make_float2(acc[mt][nt][0] + bv[2*nt], acc[mt][nt][1] + bv[2*nt+1]);
                *(float2*)&S[(size_t)(r0 + 8) * SPAD + col] =
                    make_float2(acc[mt][nt][2] + bv[2*nt], acc[mt][nt][3] + bv[2*nt+1]);
            }
        }
        __syncthreads();

        const int r = tid >> 1, h = tid & 1;
        const size_t grow = (size_t)m0 + r;
        const float* erow = EPS + grow * 128 + h * 64;
        float kla = 0.f;
        uint32_t zbuf[32];
#pragma unroll
        for (int j = 0; j < 32; ++j) {
            int c = h * 64 + 2 * j;
            float mu0 = S[(size_t)r * SPAD + c];
            float mu1 = S[(size_t)r * SPAD + c + 1];
            float l0  = S[(size_t)r * SPAD + c + 128];
            float l1  = S[(size_t)r * SPAD + c + 129];
            float2 ep = *(const float2*)&erow[2 * j];
            float s0 = __expf(l0), s1 = __expf(l1);
            float z0 = fmaf(s0, ep.x, mu0), z1 = fmaf(s1, ep.y, mu1);
            __nv_bfloat162 p = __float22bfloat162_rn(make_float2(z0, z1));
            zbuf[j] = *(uint32_t*)&p;
            kla += s0 * s0 + mu0 * mu0 - 2.f * l0 - 1.f;
            kla += s1 * s1 + mu1 * mu1 - 2.f * l1 - 1.f;
        }
        kla += __shfl_xor_sync(0xffffffffu, kla, 1);
        if (h == 0) LP[grow] = 0.5f * kla;
        __syncthreads();

        // stage z into smem as two swizzled A-chunks (16KB each, at sbase)
#pragma unroll
        for (int cc = 0; cc < 8; ++cc) {
            uint32_t off = (uint32_t)h * 16384u +
                           (uint32_t)(r * 128 + ((cc ^ (r & 7)) << 4));
            *(int4*)(sm + off) = ((int4*)zbuf)[cc];
        }

        auto issue_b = [&](int nb) {
            uint32_t sB = sbase + 32768u + (uint32_t)(nb % 3) * 32768u;
            const __nv_bfloat16* Bk = W2 + (size_t)(nb * 128) * 128;
#pragma unroll
            for (int i = 0; i < 2048 / NTHR; ++i) {
                int idx = tid + i * NTHR;
                int tt = idx >> 10;
                int rr = (idx >> 3) & 127;
                int cc = idx & 7;
                uint32_t sw = (uint32_t)(rr * 128 + ((cc ^ (rr & 7)) << 4));
                CP_ASYNC16(sB + (uint32_t)tt * 16384u + sw,
                           Bk + (size_t)rr * 128 + tt * 64 + cc * 8);
            }
            CP_COMMIT();
        };
        issue_b(0); issue_b(1);

        for (int nb = 0; nb < 8; ++nb) {
            if (nb < 7) { CP_WAIT1(); } else { CP_WAIT0(); }
            __syncthreads();
            if (nb + 2 < 8) issue_b(nb + 2);

            uint32_t sB = sbase + 32768u + (uint32_t)(nb % 3) * 32768u;
            float acc2[4][4][4];
#pragma unroll
            for (int mt = 0; mt < 4; ++mt)
#pragma unroll
                for (int nt = 0; nt < 4; ++nt)
#pragma unroll
                    for (int q = 0; q < 4; ++q) acc2[mt][nt][q] = 0.f;

#pragma unroll
            for (int t = 0; t < 2; ++t) {
#pragma unroll
                for (int kk = 0; kk < 4; ++kk) {
                    uint32_t a[4][4];
#pragma unroll
                    for (int mt = 0; mt < 4; ++mt) {
                        int row = wm * 64 + mt * 16 + (g & 1) * 8 + lq;
                        int kc  = kk * 2 + (g >> 1);
                        uint32_t ad = sbase + (uint32_t)t * 16384u +
                                      (uint32_t)(row * 128 + ((kc ^ (row & 7)) << 4));
                        ldsm4(a[mt][0], a[mt][1], a[mt][2], a[mt][3], ad);
                    }
                    uint32_t b[4][2];
#pragma unroll
                    for (int p = 0; p < 2; ++p) {
                        int row = wn * 32 + (p * 2 + (g >> 1)) * 8 + lq;
                        int kc  = kk * 2 + (g & 1);
                        uint32_t ad = sB + (uint32_t)t * 16384u +
                                      (uint32_t)(row * 128 + ((kc ^ (row & 7)) << 4));
                        uint32_t r0, r1, r2, r3;
                        ldsm4(r0, r1, r2, r3, ad);
                        b[p * 2][0] = r0; b[p * 2][1] = r1;
                        b[p * 2 + 1][0] = r2; b[p * 2 + 1][1] = r3;
                    }
#pragma unroll
                    for (int mt = 0; mt < 4; ++mt)
#pragma unroll
                        for (int nt = 0; nt < 4; ++nt)
                            mma16816(acc2[mt][nt], a[mt], b[nt]);
                }
            }
#pragma unroll
            for (int mt = 0; mt < 4; ++mt) {
                int r0 = rbase + mt * 16;
#pragma unroll
                for (int nt = 0; nt < 4; ++nt) {
                    int col = nb * 128 + wn * 32 + nt * 8 + cq;
                    float b0 = __ldg(B2 + col), b1 = __ldg(B2 + col + 1);
                    float v0 = fmaxf(acc2[mt][nt][0] + b0, 0.f);
                    float v1 = fmaxf(acc2[mt][nt][1] + b1, 0.f);
                    float v2 = fmaxf(acc2[mt][nt][2] + b0, 0.f);
                    float v3 = fmaxf(acc2[mt][nt][3] + b1, 0.f);
                    __nv_bfloat162 p0 = __float22bfloat162_rn(make_float2(v0, v1));
                    __nv_bfloat162 p1 = __float22bfloat162_rn(make_float2(v2, v3));
                    *(uint32_t*)(C2 + (size_t)r0 * D_H + col)       = *(uint32_t*)&p0;
                    *(uint32_t*)(C2 + (size_t)(r0 + 8) * D_H + col) = *(uint32_t*)&p1;
                }
            }
        }
    }
}

// ---------------- fused prep kernel ------------------------------------------
__device__ __forceinline__ void do_transpose(float (*ts)[33],
                                             const float* __restrict__ in,
                                             __nv_bfloat16* __restrict__ out,
                                             int K, int N, int rowOff, int bx, int by, int tid) {
    int tx = tid & 31, ty = tid >> 5;
    int k0 = by * 32, n0 = bx * 32;
    for (int j = ty; j < 32; j += 8)
        ts[j][tx] = in[(size_t)(k0 + j) * N + n0 + tx];
    __syncthreads();
    for (int j = ty; j < 32; j += 8)
        out[(size_t)(rowOff + n0 + j) * K + k0 + tx] = __float2bfloat16(ts[tx][j]);
}

__global__ __launch_bounds__(256)
void prep_kernel(const float* __restrict__ x,
                 const float* __restrict__ We1, const float* __restrict__ Wmu,
                 const float* __restrict__ Wls, const float* __restrict__ Wd1,
                 const float* __restrict__ Wd2, const float* __restrict__ bmu,
                 const float* __restrict__ bls,
                 __nv_bfloat16* __restrict__ xb, uint8_t* __restrict__ xbit,
                 __nv_bfloat16* __restrict__ We1t,
                 __nv_bfloat16* __restrict__ Wmlt, __nv_bfloat16* __restrict__ Wd1t,
                 __nv_bfloat16* __restrict__ Wd2t, float* __restrict__ bml)
{
    __shared__ float ts[32][33];
    const int b = blockIdx.x, tid = threadIdx.x;
    if (b < 16384) {
        size_t i = ((size_t)b * 256 + tid) * 8;
        float4 a = *(const float4*)(x + i);
        float4 c = *(const float4*)(x + i + 4);
        __nv_bfloat162 p[4];
        p[0] = __float22bfloat162_rn(make_float2(a.x, a.y));
        p[1] = __float22bfloat162_rn(make_float2(a.z, a.w));
        p[2] = __float22bfloat162_rn(make_float2(c.x, c.y));
        p[3] = __float22bfloat162_rn(make_float2(c.z, c.w));
        *(int4*)(xb + i) = *(int4*)p;
        uint32_t bits = (a.x > 0.5f ? 1u : 0u)  | (a.y > 0.5f ? 2u : 0u)
                      | (a.z > 0.5f ? 4u : 0u)  | (a.w > 0.5f ? 8u : 0u)
                      | (c.x > 0.5f ? 16u : 0u) | (c.y > 0.5f ? 32u : 0u)
                      | (c.z > 0.5f ? 64u : 0u) | (c.w > 0.5f ? 128u : 0u);
        xbit[(size_t)b * 256 + tid] = (uint8_t)bits;
    } else if (b < 17408) {
        int r = b - 16384;  do_transpose(ts, We1, We1t, 1024, 1024, 0,   r % 32, r / 32, tid);
    } else if (b < 17536) {
        int r = b - 17408;  do_transpose(ts, Wmu, Wmlt, 1024, 128,  0,   r % 4,  r / 4,  tid);
    } else if (b < 17664) {
        int r = b - 17536;  do_transpose(ts, Wls, Wmlt, 1024, 128,  128, r % 4,  r / 4,  tid);
    } else if (b < 17792) {
        int r = b - 17664;  do_transpose(ts, Wd1, Wd1t, 128,  1024, 0,   r % 32, r / 32, tid);
    } else if (b < 18816) {
        int r = b - 17792;  do_transpose(ts, Wd2, Wd2t, 1024, 1024, 0,   r % 32, r / 32, tid);
    } else {
        bml[tid] = (tid < 128) ? bmu[tid] : bls[tid - 128];
    }
}

__global__ void finalize_kernel(const float* __restrict__ kl_, const float* __restrict__ lp_,
                                float* __restrict__ out) {
    int r = blockIdx.x * blockDim.x + threadIdx.x;
    float s = 0.f;
#pragma unroll
    for (int j = 0; j < 16; j++) s += lp_[(size_t)r * 16 + j];
    out[r] = s - kl_[r];
}

// ---------------- launch ------------------------------------------------------
extern "C" void kernel_launch(void* const* d_in, const int* in_sizes, int n_in,
                              void* d_out, int out_size)
{
    const float* x   = (const float*)d_in[0];
    const float* eps = (const float*)d_in[1];
    const float* We1 = (const float*)d_in[2];
    const float* be1 = (const float*)d_in[3];
    const float* Wmu = (const float*)d_in[4];
    const float* bmu = (const float*)d_in[5];
    const float* Wls = (const float*)d_in[6];
    const float* bls = (const float*)d_in[7];
    const float* Wd1 = (const float*)d_in[8];
    const float* bd1 = (const float*)d_in[9];
    const float* Wd2 = (const float*)d_in[10];
    const float* bd2 = (const float*)d_in[11];
    float* out = (float*)d_out;

    __nv_bfloat16 *xb, *hb, *hdb, *We1t, *Wmlt, *Wd1t, *Wd2t;
    uint64_t* xbit;
    float *kl, *lp, *bml;
    cudaGetSymbolAddress((void**)&xb,   g_xb);
    cudaGetSymbolAddress((void**)&xbit, g_xbit);
    cudaGetSymbolAddress((void**)&hb,   g_hb);
    cudaGetSymbolAddress((void**)&hdb,  g_hdb);
    cudaGetSymbolAddress((void**)&kl,   g_kl);
    cudaGetSymbolAddress((void**)&lp,   g_lp);
    cudaGetSymbolAddress((void**)&We1t, g_We1t);
    cudaGetSymbolAddress((void**)&Wmlt, g_Wmlt);
    cudaGetSymbolAddress((void**)&Wd1t, g_Wd1t);
    cudaGetSymbolAddress((void**)&Wd2t, g_Wd2t);
    cudaGetSymbolAddress((void**)&bml,  g_bml);

    constexpr int SM_SMALL = GemmCfg<128,128,3>::SMEM;   // 3 x 32KB + pad
    constexpr int SM_BIG   = GemmCfg<128,256,4>::SMEM;   // 4 x 48KB + pad

    cudaFuncSetAttribute((const void*)mma_gemm<0,128,128,128,3,2>, cudaFuncAttributeMaxDynamicSharedMemorySize, SM_SMALL);
    cudaFuncSetAttribute((const void*)mma_gemm<2,128,128,128,3,2>, cudaFuncAttributeMaxDynamicSharedMemorySize, SM_SMALL);
    cudaFuncSetAttribute((const void*)mma_gemm<3,128,256,256,4,1>, cudaFuncAttributeMaxDynamicSharedMemorySize, SM_BIG);

    // 0) fused prep (also bit-packs x)
    prep_kernel<<<18817, 256>>>(x, We1, Wmu, Wls, Wd1, Wd2, bmu, bls,
                                xb, (uint8_t*)xbit, We1t, Wmlt, Wd1t, Wd2t, bml);
    // 1) h = relu(x @ We1 + be1) -> bf16
    mma_gemm<0,128,128,128,3,2><<<dim3(8, 256), 128, SM_SMALL>>>(
        xb, D_IN, We1t, be1, hb, D_H, nullptr, nullptr, nullptr,
        nullptr, nullptr, nullptr, D_IN);
    // 2) [mu|ls] GEMM + fused reparam/KL + hd = relu(z @ Wd1 + bd1) -> hdb
    mma_gemm<3,128,256,256,4,1><<<dim3(1, 256), 256, SM_BIG>>>(
        hb, D_H, Wmlt, bml, nullptr, 0, nullptr, kl, eps,
        Wd1t, bd1, hdb, D_H);
    // 3) Bernoulli log-lik partials from hd @ Wd2 + bd2 (bit-packed x)
    mma_gemm<2,128,128,128,3,2><<<dim3(8, 256), 128, SM_SMALL>>>(
        hdb, D_H, Wd2t, bd2, nullptr, 0, xbit, lp, nullptr,
        nullptr, nullptr, nullptr, D_H);
    // 4) out = log_px - kl
    finalize_kernel<<<BATCH / 256, 256>>>(kl, lp, out);
}